// round 1
// baseline (speedup 1.0000x reference)
#include <cuda_runtime.h>
#include <math.h>

// Problem constants
#define N_    8
#define M_    50000
#define FIN_  64
#define FOUT_ 64
#define K_    9

// Tiling
#define TM      256          // rows of m per block
#define THREADS 256          // 32 (m-groups) x 8 (o-groups), each thread 8m x 8o

#define SW_FLOATS (K_ * FIN_ * FOUT_)   // 36864
#define SA_FLOATS (FIN_ * TM)           // 16384
#define SIDX_INTS (K_ * TM)             // 2304
#define SMEM_BYTES ((SW_FLOATS + SA_FLOATS + SIDX_INTS) * 4)  // 222208 B

// Transposed weight scratch: Wt[k][i][o] = W[o][k*64+i]
__device__ float g_Wt[SW_FLOATS];

__global__ void transpose_w_kernel(const float* __restrict__ w) {
    int t = blockIdx.x * blockDim.x + threadIdx.x;
    if (t < SW_FLOATS) {
        int o = t & (FOUT_ - 1);
        int c = t >> 6;                 // c = k*64 + i
        g_Wt[t] = w[o * (K_ * FIN_) + c];
    }
}

__device__ __forceinline__ float elu1(float v) {
    return v > 0.0f ? v : expm1f(v);
}

__global__ __launch_bounds__(THREADS, 1)
void gconv_kernel(const float* __restrict__ x,
                  const int*   __restrict__ idx,
                  const float* __restrict__ bias,
                  float*       __restrict__ out)
{
    extern __shared__ float smem[];
    float* sW   = smem;                        // [K_][FIN_][FOUT_]
    float* sA   = smem + SW_FLOATS;            // [FIN_][TM] (transposed chunk)
    int*   sIdx = (int*)(sA + SA_FLOATS);      // [K_][TM]

    const int tid = threadIdx.x;
    const int n   = blockIdx.y;
    const int m0  = blockIdx.x * TM;

    // ---- Load full transposed weight into smem (coalesced float4) ----
    {
        const float4* wt4 = (const float4*)g_Wt;
        float4* sW4 = (float4*)sW;
        #pragma unroll
        for (int j = tid; j < SW_FLOATS / 4; j += THREADS)
            sW4[j] = wt4[j];
    }

    // ---- Stage gather indices for this block's rows ----
    {
        const int m = m0 + tid;
        const bool ok = (m < M_);
        #pragma unroll
        for (int k = 0; k < K_; k++)
            sIdx[k * TM + tid] = ok ? idx[m * K_ + k] : 0;
    }
    __syncthreads();

    const int tx = tid & 7;    // o-group: columns {4tx..4tx+3, 32+4tx..32+4tx+3}
    const int ty = tid >> 3;   // m-group: rows ty*8 .. ty*8+7

    float acc[8][8];
    #pragma unroll
    for (int i = 0; i < 8; i++)
        #pragma unroll
        for (int j = 0; j < 8; j++)
            acc[i][j] = 0.0f;

    const float* xn = x + (size_t)n * M_ * FIN_;

    for (int k = 0; k < K_; k++) {
        // ---- Gather A chunk: thread tid owns row tid (one gathered x-row) ----
        const int g = sIdx[k * TM + tid];
        const float4* src = (const float4*)(xn + (size_t)g * FIN_);
        float4 v0[8], v1[8];
        #pragma unroll
        for (int p = 0; p < 8; p++) v0[p] = src[p];
        #pragma unroll
        for (int p = 0; p < 8; p++) v1[p] = src[8 + p];

        __syncthreads();   // previous chunk's compute done before overwriting sA

        // transposed store: sA[i][row=tid]; lane->row mapping = conflict-free banks
        #pragma unroll
        for (int p = 0; p < 8; p++) {
            const int q = p * 4;
            sA[(q + 0) * TM + tid] = v0[p].x;
            sA[(q + 1) * TM + tid] = v0[p].y;
            sA[(q + 2) * TM + tid] = v0[p].z;
            sA[(q + 3) * TM + tid] = v0[p].w;
        }
        #pragma unroll
        for (int p = 0; p < 8; p++) {
            const int q = 32 + p * 4;
            sA[(q + 0) * TM + tid] = v1[p].x;
            sA[(q + 1) * TM + tid] = v1[p].y;
            sA[(q + 2) * TM + tid] = v1[p].z;
            sA[(q + 3) * TM + tid] = v1[p].w;
        }
        __syncthreads();

        // ---- FMA-bound inner product over this 64-wide K chunk ----
        const float* sWk = sW + k * (FIN_ * FOUT_);
        #pragma unroll 8
        for (int kk = 0; kk < FIN_; kk++) {
            const float4 a0 = *(const float4*)&sA[kk * TM + (ty << 3)];
            const float4 a1 = *(const float4*)&sA[kk * TM + (ty << 3) + 4];
            const float4 b0 = *(const float4*)&sWk[kk * FOUT_ + (tx << 2)];
            const float4 b1 = *(const float4*)&sWk[kk * FOUT_ + 32 + (tx << 2)];
            const float a[8] = {a0.x, a0.y, a0.z, a0.w, a1.x, a1.y, a1.z, a1.w};
            const float b[8] = {b0.x, b0.y, b0.z, b0.w, b1.x, b1.y, b1.z, b1.w};
            #pragma unroll
            for (int mi = 0; mi < 8; mi++)
                #pragma unroll
                for (int oi = 0; oi < 8; oi++)
                    acc[mi][oi] = fmaf(a[mi], b[oi], acc[mi][oi]);
        }
    }

    // ---- Epilogue: bias + ELU, coalesced float4 stores ----
    float bb[8];
    #pragma unroll
    for (int u = 0; u < 4; u++) {
        bb[u]     = bias[(tx << 2) + u];
        bb[4 + u] = bias[32 + (tx << 2) + u];
    }

    #pragma unroll
    for (int mi = 0; mi < 8; mi++) {
        const int m = m0 + (ty << 3) + mi;
        if (m < M_) {
            float* dst = out + ((size_t)(n * M_ + m)) * FOUT_;
            float4 r0, r1;
            r0.x = elu1(acc[mi][0] + bb[0]);
            r0.y = elu1(acc[mi][1] + bb[1]);
            r0.z = elu1(acc[mi][2] + bb[2]);
            r0.w = elu1(acc[mi][3] + bb[3]);
            r1.x = elu1(acc[mi][4] + bb[4]);
            r1.y = elu1(acc[mi][5] + bb[5]);
            r1.z = elu1(acc[mi][6] + bb[6]);
            r1.w = elu1(acc[mi][7] + bb[7]);
            *(float4*)(dst + (tx << 2)) = r0;
            *(float4*)(dst + 32 + (tx << 2)) = r1;
        }
    }
}

extern "C" void kernel_launch(void* const* d_in, const int* in_sizes, int n_in,
                              void* d_out, int out_size)
{
    const float* x    = (const float*)d_in[0];
    const int*   idx  = (const int*)  d_in[1];
    const float* w    = (const float*)d_in[2];
    const float* bias = (const float*)d_in[3];
    float* out = (float*)d_out;

    (void)in_sizes; (void)n_in; (void)out_size;

    cudaFuncSetAttribute(gconv_kernel,
                         cudaFuncAttributeMaxDynamicSharedMemorySize, SMEM_BYTES);

    transpose_w_kernel<<<(SW_FLOATS + 255) / 256, 256>>>(w);

    dim3 grid((M_ + TM - 1) / TM, N_);   // x-fastest => consecutive blocks share n (L2-friendly gather)
    gconv_kernel<<<grid, THREADS, SMEM_BYTES>>>(x, idx, bias, out);
}

// round 3
// speedup vs baseline: 1.1664x; 1.1664x over previous
#include <cuda_runtime.h>
#include <math.h>

// Problem constants
#define N_    8
#define M_    50000
#define FIN_  64
#define FOUT_ 64
#define K_    9

// Tiling
#define TM      128                      // m rows per tile
#define THREADS 256
#define MTILES  ((M_ + TM - 1) / TM)     // 391
#define NTILES  (N_ * MTILES)            // 3128
#define NBLOCKS 148                      // persistent CTAs, 1/SM (smem-limited)

#define SW_FLOATS (K_ * FIN_ * FOUT_)    // 36864  (147456 B)
#define SA_FLOATS (FIN_ * TM)            // 8192   (32768 B)
#define SIDX_INTS (TM * K_)              // 1152   (4608 B)
#define SMEM_BYTES ((SW_FLOATS + SA_FLOATS + SIDX_INTS) * 4)  // 184832 B

typedef unsigned long long ull;

// Transposed weight scratch: Wt[k][i][o] = W[o][k*64+i]
__device__ float g_Wt[SW_FLOATS];

__global__ void transpose_w_kernel(const float* __restrict__ w) {
    int t = blockIdx.x * blockDim.x + threadIdx.x;
    if (t < SW_FLOATS) {
        int o = t & (FOUT_ - 1);
        int c = t >> 6;                  // c = k*64 + i
        g_Wt[t] = w[o * (K_ * FIN_) + c];
    }
}

__device__ __forceinline__ ull pack2(float x) {
    ull r; asm("mov.b64 %0, {%1, %1};" : "=l"(r) : "f"(x)); return r;
}
__device__ __forceinline__ void ffma2(ull& d, ull a, ull b) {
    asm("fma.rn.f32x2 %0, %1, %2, %0;" : "+l"(d) : "l"(a), "l"(b));
}
__device__ __forceinline__ float2 unpack2(ull v) {
    float2 f; asm("mov.b64 {%0, %1}, %2;" : "=f"(f.x), "=f"(f.y) : "l"(v)); return f;
}
__device__ __forceinline__ float elu1(float v) {
    return v > 0.0f ? v : expm1f(v);
}

__global__ __launch_bounds__(THREADS, 1)
void gconv_kernel(const float* __restrict__ x,
                  const int*   __restrict__ idx,
                  const float* __restrict__ bias,
                  float*       __restrict__ out)
{
    extern __shared__ float smem[];
    float* sW   = smem;                        // [K_][FIN_][FOUT_]
    float* sA   = smem + SW_FLOATS;            // [FIN_][TM] transposed chunk
    int*   sIdx = (int*)(sA + SA_FLOATS);      // [TM][K_]

    const int tid = threadIdx.x;
    const int tx  = tid & 7;                   // o-group
    const int ty  = tid >> 3;                  // m-group: rows ty*4..ty*4+3
    const int r   = tid & (TM - 1);            // gather row owned by this thread
    const int h   = tid >> 7;                  // which half of the row (32 floats)

    // ---- Load full transposed weight into smem ONCE per persistent CTA ----
    {
        const float4* wt4 = (const float4*)g_Wt;
        float4* sW4 = (float4*)sW;
        for (int j = tid; j < SW_FLOATS / 4; j += THREADS)
            sW4[j] = wt4[j];
    }

    // bias fragment (registers, loaded once)
    float bb[8];
    #pragma unroll
    for (int u = 0; u < 4; u++) {
        bb[u]     = bias[(tx << 2) + u];
        bb[4 + u] = bias[32 + (tx << 2) + u];
    }

    // ---- Persistent tile loop: tile = n * MTILES + mt ----
    for (int tile = blockIdx.x; tile < NTILES; tile += gridDim.x) {
        const int n  = tile / MTILES;
        const int mt = tile - n * MTILES;
        const int m0 = mt * TM;
        const float* xn = x + (size_t)n * M_ * FIN_;

        __syncthreads();   // previous tile fully done (sA, sIdx reads complete)

        // stage gather indices for this tile
        for (int j = tid; j < SIDX_INTS; j += THREADS) {
            int gi = m0 * K_ + j;
            sIdx[j] = (gi < M_ * K_) ? idx[gi] : 0;
        }
        __syncthreads();

        // prologue: gather chunk k=0 into registers
        float4 v[8];
        {
            const int g = sIdx[r * K_ + 0];
            const float4* src = (const float4*)(xn + (size_t)g * FIN_ + (h << 5));
            #pragma unroll
            for (int p = 0; p < 8; p++) v[p] = src[p];
        }

        ull acc[4][4];
        #pragma unroll
        for (int a = 0; a < 4; a++)
            #pragma unroll
            for (int b = 0; b < 4; b++)
                acc[a][b] = 0ull;

        for (int k = 0; k < K_; k++) {
            __syncthreads();   // compute(k-1) done before overwriting sA

            // transposed store: sA[i][r]; warp = 32 consecutive r -> conflict-free
            #pragma unroll
            for (int p = 0; p < 8; p++) {
                const int q = (h << 5) + (p << 2);
                sA[(q + 0) * TM + r] = v[p].x;
                sA[(q + 1) * TM + r] = v[p].y;
                sA[(q + 2) * TM + r] = v[p].z;
                sA[(q + 3) * TM + r] = v[p].w;
            }
            __syncthreads();

            // prefetch next chunk's gather; latency hidden by compute below
            float4 w[8];
            if (k + 1 < K_) {
                const int g = sIdx[r * K_ + (k + 1)];
                const float4* src = (const float4*)(xn + (size_t)g * FIN_ + (h << 5));
                #pragma unroll
                for (int p = 0; p < 8; p++) w[p] = src[p];
            }

            // ---- FFMA2 inner product over the 64-wide chunk ----
            const float* sWk = sW + k * (FIN_ * FOUT_);
            #pragma unroll 16
            for (int kk = 0; kk < FIN_; kk++) {
                const float4 a4 = *(const float4*)&sA[kk * TM + (ty << 2)];
                const ull* bp = (const ull*)&sWk[kk * FOUT_ + (tx << 2)];
                const ull* bq = (const ull*)&sWk[kk * FOUT_ + 32 + (tx << 2)];
                const ull b0 = bp[0], b1 = bp[1];
                const ull b2 = bq[0], b3 = bq[1];
                const ull aa0 = pack2(a4.x), aa1 = pack2(a4.y);
                const ull aa2 = pack2(a4.z), aa3 = pack2(a4.w);
                ffma2(acc[0][0], aa0, b0); ffma2(acc[0][1], aa0, b1);
                ffma2(acc[0][2], aa0, b2); ffma2(acc[0][3], aa0, b3);
                ffma2(acc[1][0], aa1, b0); ffma2(acc[1][1], aa1, b1);
                ffma2(acc[1][2], aa1, b2); ffma2(acc[1][3], aa1, b3);
                ffma2(acc[2][0], aa2, b0); ffma2(acc[2][1], aa2, b1);
                ffma2(acc[2][2], aa2, b2); ffma2(acc[2][3], aa2, b3);
                ffma2(acc[3][0], aa3, b0); ffma2(acc[3][1], aa3, b1);
                ffma2(acc[3][2], aa3, b2); ffma2(acc[3][3], aa3, b3);
            }

            if (k + 1 < K_) {
                #pragma unroll
                for (int p = 0; p < 8; p++) v[p] = w[p];
            }
        }

        // ---- Epilogue: bias + ELU, coalesced float4 stores ----
        #pragma unroll
        for (int mi = 0; mi < 4; mi++) {
            const int m = m0 + (ty << 2) + mi;
            if (m < M_) {
                float* dst = out + ((size_t)n * M_ + m) * FOUT_;
                const float2 p0 = unpack2(acc[mi][0]);
                const float2 p1 = unpack2(acc[mi][1]);
                const float2 p2 = unpack2(acc[mi][2]);
                const float2 p3 = unpack2(acc[mi][3]);
                float4 r0, r1;
                r0.x = elu1(p0.x + bb[0]);  r0.y = elu1(p0.y + bb[1]);
                r0.z = elu1(p1.x + bb[2]);  r0.w = elu1(p1.y + bb[3]);
                r1.x = elu1(p2.x + bb[4]);  r1.y = elu1(p2.y + bb[5]);
                r1.z = elu1(p3.x + bb[6]);  r1.w = elu1(p3.y + bb[7]);
                *(float4*)(dst + (tx << 2))      = r0;
                *(float4*)(dst + 32 + (tx << 2)) = r1;
            }
        }
    }
}

extern "C" void kernel_launch(void* const* d_in, const int* in_sizes, int n_in,
                              void* d_out, int out_size)
{
    const float* x    = (const float*)d_in[0];
    const int*   idx  = (const int*)  d_in[1];
    const float* w    = (const float*)d_in[2];
    const float* bias = (const float*)d_in[3];
    float* out = (float*)d_out;

    (void)in_sizes; (void)n_in; (void)out_size;

    cudaFuncSetAttribute(gconv_kernel,
                         cudaFuncAttributeMaxDynamicSharedMemorySize, SMEM_BYTES);

    transpose_w_kernel<<<(SW_FLOATS + 255) / 256, 256>>>(w);
    gconv_kernel<<<NBLOCKS, THREADS, SMEM_BYTES>>>(x, idx, bias, out);
}

// round 6
// speedup vs baseline: 1.7880x; 1.5329x over previous
#include <cuda_runtime.h>
#include <cuda_bf16.h>
#include <math.h>
#include <stdint.h>

// ---------------- problem constants ----------------
#define N_    8
#define M_    50000
#define FIN_  64
#define FOUT_ 64
#define K_    9          // gather fan-in (9 chunks of 64)
#define TM    128        // m rows per tile
#define THREADS 256      // 8 warps; warp w owns rows [w*16, w*16+16)
#define MTILES  ((M_ + TM - 1) / TM)      // 391
#define NTILES  (N_ * MTILES)             // 3128
#define NBLOCKS 148

// ---------------- smem layout (bytes) ----------------
// W (split)  : [2 halves][9 chunks][64 rows(o) x 128B] = 147456
// A (split)  : [2 bufs][hi 16384 | lo 16384]           =  65536
// idx        : 128*9*4                                 =   4608
#define SB_OFF    0
#define SA_OFF    147456
#define SIDX_OFF  212992
#define SMEM_BYTES 217600

#define SWZ(b) ((b) ^ (((b) >> 3) & 0x70))

// ---------------- ptx helpers ----------------
__device__ __forceinline__ uint32_t smem_u32(const void* p) {
    uint32_t a;
    asm("{ .reg .u64 t; cvta.to.shared.u64 t, %1; cvt.u32.u64 %0, t; }" : "=r"(a) : "l"(p));
    return a;
}
__device__ __forceinline__ void ldsm4(uint32_t* r, uint32_t addr) {
    asm volatile("ldmatrix.sync.aligned.m8n8.x4.shared.b16 {%0,%1,%2,%3}, [%4];"
                 : "=r"(r[0]), "=r"(r[1]), "=r"(r[2]), "=r"(r[3]) : "r"(addr));
}
__device__ __forceinline__ void mma16816(float* c, const uint32_t* a, uint32_t b0, uint32_t b1) {
    asm volatile("mma.sync.aligned.m16n8k16.row.col.f32.bf16.bf16.f32 "
                 "{%0,%1,%2,%3},{%4,%5,%6,%7},{%8,%9},{%0,%1,%2,%3};"
                 : "+f"(c[0]), "+f"(c[1]), "+f"(c[2]), "+f"(c[3])
                 : "r"(a[0]), "r"(a[1]), "r"(a[2]), "r"(a[3]), "r"(b0), "r"(b1));
}
// bf16x2 pack: low half = a (lower address), high half = b
__device__ __forceinline__ uint32_t bf2(float a, float b) {
    uint32_t r; asm("cvt.rn.bf16x2.f32 %0, %1, %2;" : "=r"(r) : "f"(b), "f"(a)); return r;
}
__device__ __forceinline__ float lowf(uint32_t p)  { return __uint_as_float(p << 16); }
__device__ __forceinline__ float highf(uint32_t p) { return __uint_as_float(p & 0xFFFF0000u); }
__device__ __forceinline__ float elu1(float v) { return v > 0.0f ? v : expm1f(v); }

// ---------------- weight split scratch: [half][k][o][i] bf16 ----------------
#define WELEMS (K_ * FOUT_ * FIN_)        // 36864
__device__ __nv_bfloat16 g_Wbf[2 * WELEMS];

__global__ void prep_w_kernel(const float* __restrict__ w) {
    int t = blockIdx.x * blockDim.x + threadIdx.x;
    if (t < WELEMS) {
        int k = t >> 12;                  // /4096
        int rr = t & 4095;
        int o = rr >> 6, i = rr & 63;
        float v = w[o * (K_ * FIN_) + k * FIN_ + i];
        __nv_bfloat16 hi = __float2bfloat16_rn(v);
        float lo = v - __bfloat162float(hi);
        g_Wbf[t]          = hi;
        g_Wbf[WELEMS + t] = __float2bfloat16_rn(lo);
    }
}

// ---------------- main kernel ----------------
__global__ __launch_bounds__(THREADS, 1)
void gconv_mma_kernel(const float* __restrict__ x,
                      const int*   __restrict__ idx,
                      const float* __restrict__ bias,
                      float*       __restrict__ out)
{
    extern __shared__ char smem[];
    const uint32_t sb = smem_u32(smem);
    const int tid  = threadIdx.x;
    const int wid  = tid >> 5;
    const int lane = tid & 31;
    const int r = tid & (TM - 1);          // gathered row owned (convert role)
    const int h = tid >> 7;                // half-row (32 floats)

    int* sIdx = (int*)(smem + SIDX_OFF);

    // ---- stage split weights into smem with swizzle (once per persistent CTA) ----
    for (int j = tid; j < 2 * K_ * 512; j += THREADS) {     // 16B units
        uint4 v = ((const uint4*)g_Wbf)[j];
        int t8k = j >> 9, u = j & 511;                       // 8KB tile, unit within
        *(uint4*)(smem + SB_OFF + t8k * 8192 + SWZ(u * 16)) = v;
    }

    // bias fragment: per n-group ng, this thread's 2 columns
    float bb0[8], bb1[8];
    #pragma unroll
    for (int ng = 0; ng < 8; ng++) {
        int col = ng * 8 + (lane & 3) * 2;
        bb0[ng] = bias[col];
        bb1[ng] = bias[col + 1];
    }
    __syncthreads();

    // ldmatrix base offsets (bytes, pre-swizzle)
    const uint32_t aoffB = (uint32_t)((wid * 16 + (lane & 15)) * 128 + (lane >> 4) * 16);
    const uint32_t boffB = (uint32_t)((((lane >> 4) & 1) * 8 + (lane & 7)) * 128
                                      + ((lane >> 3) & 1) * 16);

    for (int tile = blockIdx.x; tile < NTILES; tile += gridDim.x) {
        const int n  = tile / MTILES;
        const int mt = tile - n * MTILES;
        const int m0 = mt * TM;
        const float* xn = x + (size_t)n * M_ * FIN_;

        __syncthreads();   // prev tile: smem A reads done (mma) before idx/A overwrite
        for (int j = tid; j < TM * K_; j += THREADS) {
            int gi = m0 * K_ + j;
            sIdx[j] = (gi < M_ * K_) ? idx[gi] : 0;
        }
        __syncthreads();

        // gather + convert chunk 0 into buf 0
        float4 v[8];
        {
            const int g = sIdx[r * K_];
            const float4* s = (const float4*)(xn + (size_t)g * FIN_ + (h << 5));
            #pragma unroll
            for (int p = 0; p < 8; p++) v[p] = s[p];
        }

        float acc[8][4];
        #pragma unroll
        for (int a = 0; a < 8; a++)
            #pragma unroll
            for (int c = 0; c < 4; c++) acc[a][c] = 0.0f;

        // convert chunk 0
        {
            const uint32_t abase = SA_OFF;
            #pragma unroll
            for (int u = 0; u < 4; u++) {
                float4 a0 = v[2 * u], a1 = v[2 * u + 1];
                uint32_t p0 = bf2(a0.x, a0.y), p1 = bf2(a0.z, a0.w);
                uint32_t p2 = bf2(a1.x, a1.y), p3 = bf2(a1.z, a1.w);
                uint32_t q0 = bf2(a0.x - lowf(p0), a0.y - highf(p0));
                uint32_t q1 = bf2(a0.z - lowf(p1), a0.w - highf(p1));
                uint32_t q2 = bf2(a1.x - lowf(p2), a1.y - highf(p2));
                uint32_t q3 = bf2(a1.z - lowf(p3), a1.w - highf(p3));
                const int off = SWZ(r * 128 + h * 64 + u * 16);
                *(uint4*)(smem + abase + off)         = make_uint4(p0, p1, p2, p3);
                *(uint4*)(smem + abase + 16384 + off) = make_uint4(q0, q1, q2, q3);
            }
        }
        __syncthreads();

        for (int k = 0; k < K_; k++) {
            const int b = k & 1;

            // prefetch next chunk's gather (latency hidden under mma below)
            if (k + 1 < K_) {
                const int g = sIdx[r * K_ + k + 1];
                const float4* s = (const float4*)(xn + (size_t)g * FIN_ + (h << 5));
                #pragma unroll
                for (int p = 0; p < 8; p++) v[p] = s[p];
            }

            // ---- mma chunk k from buf b ----
            const uint32_t aHi = sb + SA_OFF + b * 32768;
            const uint32_t aLo = aHi + 16384;
            const uint32_t wHi = sb + SB_OFF + k * 8192;
            const uint32_t wLo = sb + SB_OFF + (K_ + k) * 8192;

            #pragma unroll
            for (int ks = 0; ks < 4; ks++) {
                uint32_t ah[4], al[4];
                ldsm4(ah, aHi + SWZ(aoffB + ks * 32));
                ldsm4(al, aLo + SWZ(aoffB + ks * 32));
                #pragma unroll
                for (int nb = 0; nb < 4; nb++) {
                    uint32_t bh[4], bl[4];
                    const uint32_t bo = boffB + nb * 2048 + ks * 32;
                    ldsm4(bh, wHi + SWZ(bo));
                    ldsm4(bl, wLo + SWZ(bo));
                    mma16816(acc[2 * nb],     ah, bh[0], bh[1]);   // Ah*Wh
                    mma16816(acc[2 * nb + 1], ah, bh[2], bh[3]);
                    mma16816(acc[2 * nb],     ah, bl[0], bl[1]);   // Ah*Wl
                    mma16816(acc[2 * nb + 1], ah, bl[2], bl[3]);
                    mma16816(acc[2 * nb],     al, bh[0], bh[1]);   // Al*Wh
                    mma16816(acc[2 * nb + 1], al, bh[2], bh[3]);
                }
            }

            // ---- convert chunk k+1 into buf b^1 (other warps may still mma buf b) ----
            if (k + 1 < K_) {
                const uint32_t abase = SA_OFF + (b ^ 1) * 32768;
                #pragma unroll
                for (int u = 0; u < 4; u++) {
                    float4 a0 = v[2 * u], a1 = v[2 * u + 1];
                    uint32_t p0 = bf2(a0.x, a0.y), p1 = bf2(a0.z, a0.w);
                    uint32_t p2 = bf2(a1.x, a1.y), p3 = bf2(a1.z, a1.w);
                    uint32_t q0 = bf2(a0.x - lowf(p0), a0.y - highf(p0));
                    uint32_t q1 = bf2(a0.z - lowf(p1), a0.w - highf(p1));
                    uint32_t q2 = bf2(a1.x - lowf(p2), a1.y - highf(p2));
                    uint32_t q3 = bf2(a1.z - lowf(p3), a1.w - highf(p3));
                    const int off = SWZ(r * 128 + h * 64 + u * 16);
                    *(uint4*)(smem + abase + off)         = make_uint4(p0, p1, p2, p3);
                    *(uint4*)(smem + abase + 16384 + off) = make_uint4(q0, q1, q2, q3);
                }
                __syncthreads();   // buf b^1 ready for chunk k+1's mma on all warps
            }
        }

        // ---- epilogue: bias + ELU straight from accumulators ----
        const int row0 = m0 + wid * 16 + (lane >> 2);
        const int colq = (lane & 3) * 2;
        #pragma unroll
        for (int ng = 0; ng < 8; ng++) {
            const int col = ng * 8 + colq;
            if (row0 < M_) {
                float* d0 = out + ((size_t)n * M_ + row0) * FOUT_ + col;
                float2 o0;
                o0.x = elu1(acc[ng][0] + bb0[ng]);
                o0.y = elu1(acc[ng][1] + bb1[ng]);
                *(float2*)d0 = o0;
            }
            if (row0 + 8 < M_) {
                float* d1 = out + ((size_t)n * M_ + row0 + 8) * FOUT_ + col;
                float2 o1;
                o1.x = elu1(acc[ng][2] + bb0[ng]);
                o1.y = elu1(acc[ng][3] + bb1[ng]);
                *(float2*)d1 = o1;
            }
        }
    }
}

extern "C" void kernel_launch(void* const* d_in, const int* in_sizes, int n_in,
                              void* d_out, int out_size)
{
    const float* x    = (const float*)d_in[0];
    const int*   idx  = (const int*)  d_in[1];
    const float* w    = (const float*)d_in[2];
    const float* bias = (const float*)d_in[3];
    float* out = (float*)d_out;

    (void)in_sizes; (void)n_in; (void)out_size;

    cudaFuncSetAttribute(gconv_mma_kernel,
                         cudaFuncAttributeMaxDynamicSharedMemorySize, SMEM_BYTES);

    prep_w_kernel<<<(WELEMS + 255) / 256, 256>>>(w);
    gconv_mma_kernel<<<NBLOCKS, THREADS, SMEM_BYTES>>>(x, idx, bias, out);
}

// round 7
// speedup vs baseline: 1.8427x; 1.0306x over previous
#include <cuda_runtime.h>
#include <cuda_bf16.h>
#include <math.h>
#include <stdint.h>

// ---------------- problem constants ----------------
#define N_    8
#define M_    50000
#define FIN_  64
#define FOUT_ 64
#define K_    9          // gather fan-in (9 chunks of 64)
#define TM    128        // m rows per tile
#define THREADS 512      // 16 warps: (wid&7)=m-group, (wid>>3)=n-half
#define MTILES  ((M_ + TM - 1) / TM)      // 391
#define NTILES  (N_ * MTILES)             // 3128
#define NBLOCKS 148

// ---------------- smem layout (bytes) ----------------
// W (split)  : [2 halves][9 chunks][64 rows(o) x 128B] = 147456
// A (split)  : [2 bufs][hi 16384 | lo 16384]           =  65536
// idx        : 128*9*4                                 =   4608
#define SB_OFF    0
#define SA_OFF    147456
#define SIDX_OFF  212992
#define SMEM_BYTES 217600

#define SWZ(b) ((b) ^ (((b) >> 3) & 0x70))

// ---------------- ptx helpers ----------------
__device__ __forceinline__ uint32_t smem_u32(const void* p) {
    uint32_t a;
    asm("{ .reg .u64 t; cvta.to.shared.u64 t, %1; cvt.u32.u64 %0, t; }" : "=r"(a) : "l"(p));
    return a;
}
__device__ __forceinline__ void ldsm4(uint32_t* r, uint32_t addr) {
    asm volatile("ldmatrix.sync.aligned.m8n8.x4.shared.b16 {%0,%1,%2,%3}, [%4];"
                 : "=r"(r[0]), "=r"(r[1]), "=r"(r[2]), "=r"(r[3]) : "r"(addr));
}
__device__ __forceinline__ void mma16816(float* c, const uint32_t* a, uint32_t b0, uint32_t b1) {
    asm volatile("mma.sync.aligned.m16n8k16.row.col.f32.bf16.bf16.f32 "
                 "{%0,%1,%2,%3},{%4,%5,%6,%7},{%8,%9},{%0,%1,%2,%3};"
                 : "+f"(c[0]), "+f"(c[1]), "+f"(c[2]), "+f"(c[3])
                 : "r"(a[0]), "r"(a[1]), "r"(a[2]), "r"(a[3]), "r"(b0), "r"(b1));
}
// bf16x2 pack: low half = a (lower address), high half = b
__device__ __forceinline__ uint32_t bf2(float a, float b) {
    uint32_t r; asm("cvt.rn.bf16x2.f32 %0, %1, %2;" : "=r"(r) : "f"(b), "f"(a)); return r;
}
__device__ __forceinline__ float lowf(uint32_t p)  { return __uint_as_float(p << 16); }
__device__ __forceinline__ float highf(uint32_t p) { return __uint_as_float(p & 0xFFFF0000u); }
__device__ __forceinline__ float elu1(float v) { return v > 0.0f ? v : expm1f(v); }

// ---------------- weight split scratch: [half][k][o][i] bf16 ----------------
#define WELEMS (K_ * FOUT_ * FIN_)        // 36864
__device__ __nv_bfloat16 g_Wbf[2 * WELEMS];

__global__ void prep_w_kernel(const float* __restrict__ w) {
    int t = blockIdx.x * blockDim.x + threadIdx.x;
    if (t < WELEMS) {
        int k = t >> 12;                  // /4096
        int rr = t & 4095;
        int o = rr >> 6, i = rr & 63;
        float v = w[o * (K_ * FIN_) + k * FIN_ + i];
        __nv_bfloat16 hi = __float2bfloat16_rn(v);
        float lo = v - __bfloat162float(hi);
        g_Wbf[t]          = hi;
        g_Wbf[WELEMS + t] = __float2bfloat16_rn(lo);
    }
}

// ---------------- main kernel ----------------
__global__ __launch_bounds__(THREADS, 1)
void gconv_mma_kernel(const float* __restrict__ x,
                      const int*   __restrict__ idx,
                      const float* __restrict__ bias,
                      float*       __restrict__ out)
{
    extern __shared__ char smem[];
    const uint32_t sb = smem_u32(smem);
    const int tid  = threadIdx.x;
    const int wid  = tid >> 5;
    const int lane = tid & 31;
    const int mwid = wid & 7;              // m-group: rows mwid*16..+16
    const int nh   = wid >> 3;             // n-half: cols nh*32..+32
    const int rr   = tid & 127;            // convert role: gathered row
    const int q    = tid >> 7;             // quarter of row (16 floats)

    int* sIdx = (int*)(smem + SIDX_OFF);

    // ---- stage split weights into smem with swizzle (once per persistent CTA) ----
    for (int j = tid; j < 2 * K_ * 512; j += THREADS) {     // 16B units
        uint4 v = ((const uint4*)g_Wbf)[j];
        int t8k = j >> 9, u = j & 511;                       // 8KB tile, unit within
        *(uint4*)(smem + SB_OFF + t8k * 8192 + SWZ(u * 16)) = v;
    }

    // bias fragment: per n-group ng (cols nh*32 + ng*8 + (lane&3)*2)
    float bb0[4], bb1[4];
    #pragma unroll
    for (int ng = 0; ng < 4; ng++) {
        int col = nh * 32 + ng * 8 + (lane & 3) * 2;
        bb0[ng] = bias[col];
        bb1[ng] = bias[col + 1];
    }
    __syncthreads();

    // ldmatrix base offsets (bytes, pre-swizzle)
    const uint32_t aoffB = (uint32_t)((mwid * 16 + (lane & 15)) * 128 + (lane >> 4) * 16);
    const uint32_t boffB = (uint32_t)((((lane >> 4) & 1) * 8 + (lane & 7)) * 128
                                      + ((lane >> 3) & 1) * 16);

    for (int tile = blockIdx.x; tile < NTILES; tile += gridDim.x) {
        const int n  = tile / MTILES;
        const int mt = tile - n * MTILES;
        const int m0 = mt * TM;
        const float* xn = x + (size_t)n * M_ * FIN_;

        __syncthreads();   // prev tile: smem A reads done before idx/A overwrite
        for (int j = tid; j < TM * K_; j += THREADS) {
            int gi = m0 * K_ + j;
            sIdx[j] = (gi < M_ * K_) ? idx[gi] : 0;
        }
        __syncthreads();

        // gather chunk 0 (this thread's quarter of row rr)
        float4 v[4];
        {
            const int g = sIdx[rr * K_];
            const float4* s = (const float4*)(xn + (size_t)g * FIN_ + (q << 4));
            #pragma unroll
            for (int p = 0; p < 4; p++) v[p] = s[p];
        }

        float acc[4][4];
        #pragma unroll
        for (int a = 0; a < 4; a++)
            #pragma unroll
            for (int c = 0; c < 4; c++) acc[a][c] = 0.0f;

        // convert chunk 0 into buf 0
        {
            const uint32_t abase = SA_OFF;
            #pragma unroll
            for (int u = 0; u < 2; u++) {
                float4 a0 = v[2 * u], a1 = v[2 * u + 1];
                uint32_t p0 = bf2(a0.x, a0.y), p1 = bf2(a0.z, a0.w);
                uint32_t p2 = bf2(a1.x, a1.y), p3 = bf2(a1.z, a1.w);
                uint32_t q0 = bf2(a0.x - lowf(p0), a0.y - highf(p0));
                uint32_t q1 = bf2(a0.z - lowf(p1), a0.w - highf(p1));
                uint32_t q2 = bf2(a1.x - lowf(p2), a1.y - highf(p2));
                uint32_t q3 = bf2(a1.z - lowf(p3), a1.w - highf(p3));
                const int off = SWZ(rr * 128 + q * 32 + u * 16);
                *(uint4*)(smem + abase + off)         = make_uint4(p0, p1, p2, p3);
                *(uint4*)(smem + abase + 16384 + off) = make_uint4(q0, q1, q2, q3);
            }
        }
        __syncthreads();

        for (int k = 0; k < K_; k++) {
            const int b = k & 1;

            // prefetch next chunk's gather (latency hidden under mma below)
            if (k + 1 < K_) {
                const int g = sIdx[rr * K_ + k + 1];
                const float4* s = (const float4*)(xn + (size_t)g * FIN_ + (q << 4));
                #pragma unroll
                for (int p = 0; p < 4; p++) v[p] = s[p];
            }

            // ---- mma chunk k from buf b (this warp: 16 rows x 32 cols) ----
            const uint32_t aHi = sb + SA_OFF + b * 32768;
            const uint32_t aLo = aHi + 16384;
            const uint32_t wHi = sb + SB_OFF + k * 8192;
            const uint32_t wLo = sb + SB_OFF + (K_ + k) * 8192;

            #pragma unroll
            for (int ks = 0; ks < 4; ks++) {
                uint32_t ah[4], al[4];
                ldsm4(ah, aHi + SWZ(aoffB + ks * 32));
                ldsm4(al, aLo + SWZ(aoffB + ks * 32));
                #pragma unroll
                for (int nb = 0; nb < 2; nb++) {
                    uint32_t bh[4], bl[4];
                    const uint32_t bo = boffB + (nh * 2 + nb) * 2048 + ks * 32;
                    ldsm4(bh, wHi + SWZ(bo));
                    ldsm4(bl, wLo + SWZ(bo));
                    mma16816(acc[2 * nb],     ah, bh[0], bh[1]);   // Ah*Wh
                    mma16816(acc[2 * nb + 1], ah, bh[2], bh[3]);
                    mma16816(acc[2 * nb],     ah, bl[0], bl[1]);   // Ah*Wl
                    mma16816(acc[2 * nb + 1], ah, bl[2], bl[3]);
                    mma16816(acc[2 * nb],     al, bh[0], bh[1]);   // Al*Wh
                    mma16816(acc[2 * nb + 1], al, bh[2], bh[3]);
                }
            }

            // ---- convert chunk k+1 into buf b^1 ----
            if (k + 1 < K_) {
                const uint32_t abase = SA_OFF + (b ^ 1) * 32768;
                #pragma unroll
                for (int u = 0; u < 2; u++) {
                    float4 a0 = v[2 * u], a1 = v[2 * u + 1];
                    uint32_t p0 = bf2(a0.x, a0.y), p1 = bf2(a0.z, a0.w);
                    uint32_t p2 = bf2(a1.x, a1.y), p3 = bf2(a1.z, a1.w);
                    uint32_t q0 = bf2(a0.x - lowf(p0), a0.y - highf(p0));
                    uint32_t q1 = bf2(a0.z - lowf(p1), a0.w - highf(p1));
                    uint32_t q2 = bf2(a1.x - lowf(p2), a1.y - highf(p2));
                    uint32_t q3 = bf2(a1.z - lowf(p3), a1.w - highf(p3));
                    const int off = SWZ(rr * 128 + q * 32 + u * 16);
                    *(uint4*)(smem + abase + off)         = make_uint4(p0, p1, p2, p3);
                    *(uint4*)(smem + abase + 16384 + off) = make_uint4(q0, q1, q2, q3);
                }
                __syncthreads();   // buf b^1 ready on all warps
            }
        }

        // ---- epilogue: bias + ELU straight from accumulators ----
        const int row0 = m0 + mwid * 16 + (lane >> 2);
        const int colq = nh * 32 + (lane & 3) * 2;
        #pragma unroll
        for (int ng = 0; ng < 4; ng++) {
            const int col = colq + ng * 8;
            if (row0 < M_) {
                float* d0 = out + ((size_t)n * M_ + row0) * FOUT_ + col;
                float2 o0;
                o0.x = elu1(acc[ng][0] + bb0[ng]);
                o0.y = elu1(acc[ng][1] + bb1[ng]);
                *(float2*)d0 = o0;
            }
            if (row0 + 8 < M_) {
                float* d1 = out + ((size_t)n * M_ + row0 + 8) * FOUT_ + col;
                float2 o1;
                o1.x = elu1(acc[ng][2] + bb0[ng]);
                o1.y = elu1(acc[ng][3] + bb1[ng]);
                *(float2*)d1 = o1;
            }
        }
    }
}

extern "C" void kernel_launch(void* const* d_in, const int* in_sizes, int n_in,
                              void* d_out, int out_size)
{
    const float* x    = (const float*)d_in[0];
    const int*   idx  = (const int*)  d_in[1];
    const float* w    = (const float*)d_in[2];
    const float* bias = (const float*)d_in[3];
    float* out = (float*)d_out;

    (void)in_sizes; (void)n_in; (void)out_size;

    cudaFuncSetAttribute(gconv_mma_kernel,
                         cudaFuncAttributeMaxDynamicSharedMemorySize, SMEM_BYTES);

    prep_w_kernel<<<(WELEMS + 255) / 256, 256>>>(w);
    gconv_mma_kernel<<<NBLOCKS, THREADS, SMEM_BYTES>>>(x, idx, bias, out);
}

// round 9
// speedup vs baseline: 2.9643x; 1.6087x over previous
#include <cuda_runtime.h>
#include <cuda_bf16.h>
#include <math.h>
#include <stdint.h>

// ---------------- problem constants ----------------
#define N_    8
#define M_    50000
#define FIN_  64
#define FOUT_ 64
#define K_    9          // gather fan-in (9 chunks of 64)
#define TM    128        // m rows per tile
#define THREADS 512      // 16 warps: (wid&7)=m-group, (wid>>3)=n-half
#define MTILES  ((M_ + TM - 1) / TM)      // 391
#define NTILES  (N_ * MTILES)             // 3128
#define NBLOCKS 148

// ---------------- smem layout (bytes) ----------------
// W (split)  : [2 halves][9 chunks][64 rows(o) x 128B] = 147456
// A (split)  : [2 bufs][hi 16384 | lo 16384]           =  65536
// idx        : 128*9*4                                 =   4608
#define SB_OFF    0
#define SA_OFF    147456
#define SIDX_OFF  212992
#define SMEM_BYTES 217600

#define SWZ(b) ((b) ^ (((b) >> 3) & 0x70))

// ---------------- ptx helpers ----------------
__device__ __forceinline__ uint32_t smem_u32(const void* p) {
    uint32_t a;
    asm("{ .reg .u64 t; cvta.to.shared.u64 t, %1; cvt.u32.u64 %0, t; }" : "=r"(a) : "l"(p));
    return a;
}
__device__ __forceinline__ void ldsm4(uint32_t* r, uint32_t addr) {
    asm volatile("ldmatrix.sync.aligned.m8n8.x4.shared.b16 {%0,%1,%2,%3}, [%4];"
                 : "=r"(r[0]), "=r"(r[1]), "=r"(r[2]), "=r"(r[3]) : "r"(addr));
}
__device__ __forceinline__ void mma16816(float* c, const uint32_t* a, uint32_t b0, uint32_t b1) {
    asm volatile("mma.sync.aligned.m16n8k16.row.col.f32.bf16.bf16.f32 "
                 "{%0,%1,%2,%3},{%4,%5,%6,%7},{%8,%9},{%0,%1,%2,%3};"
                 : "+f"(c[0]), "+f"(c[1]), "+f"(c[2]), "+f"(c[3])
                 : "r"(a[0]), "r"(a[1]), "r"(a[2]), "r"(a[3]), "r"(b0), "r"(b1));
}
// bf16x2 pack: low half = a (lower address), high half = b
__device__ __forceinline__ uint32_t bf2(float a, float b) {
    uint32_t r; asm("cvt.rn.bf16x2.f32 %0, %1, %2;" : "=r"(r) : "f"(b), "f"(a)); return r;
}
__device__ __forceinline__ float lowf(uint32_t p)  { return __uint_as_float(p << 16); }
__device__ __forceinline__ float highf(uint32_t p) { return __uint_as_float(p & 0xFFFF0000u); }
__device__ __forceinline__ float elu1(float v) { return v > 0.0f ? v : expm1f(v); }

// ---------------- weight split scratch: [half][k][o][i] bf16 ----------------
#define WELEMS (K_ * FOUT_ * FIN_)        // 36864
__device__ __nv_bfloat16 g_Wbf[2 * WELEMS];

__global__ void prep_w_kernel(const float* __restrict__ w) {
    int t = blockIdx.x * blockDim.x + threadIdx.x;
    if (t < WELEMS) {
        int k = t >> 12;                  // /4096
        int rr = t & 4095;
        int o = rr >> 6, i = rr & 63;
        float v = w[o * (K_ * FIN_) + k * FIN_ + i];
        __nv_bfloat16 hi = __float2bfloat16_rn(v);
        float lo = v - __bfloat162float(hi);
        g_Wbf[t]          = hi;
        g_Wbf[WELEMS + t] = __float2bfloat16_rn(lo);
    }
}

// ---------------- main kernel ----------------
__global__ __launch_bounds__(THREADS, 1)
void gconv_mma_kernel(const float* __restrict__ x,
                      const int*   __restrict__ idx,
                      const float* __restrict__ bias,
                      float*       __restrict__ out)
{
    extern __shared__ char smem[];
    const uint32_t sb = smem_u32(smem);
    const int tid  = threadIdx.x;
    const int wid  = tid >> 5;
    const int lane = tid & 31;
    const int mwid = wid & 7;              // m-group: rows mwid*16..+16
    const int nh   = wid >> 3;             // n-half: cols nh*32..+32
    const int grow = tid >> 4;             // gather: row group 0..31
    const int ql   = tid & 15;             // gather: 16B slice within the row

    int* sIdx = (int*)(smem + SIDX_OFF);

    // ---- stage split weights into smem with swizzle (once per persistent CTA) ----
    for (int j = tid; j < 2 * K_ * 512; j += THREADS) {     // 16B units
        uint4 v = ((const uint4*)g_Wbf)[j];
        int t8k = j >> 9, u = j & 511;                       // 8KB tile, unit within
        *(uint4*)(smem + SB_OFF + t8k * 8192 + SWZ(u * 16)) = v;
    }

    // bias fragment: per n-group ng (cols nh*32 + ng*8 + (lane&3)*2)
    float bb0[4], bb1[4];
    #pragma unroll
    for (int ng = 0; ng < 4; ng++) {
        int col = nh * 32 + ng * 8 + (lane & 3) * 2;
        bb0[ng] = bias[col];
        bb1[ng] = bias[col + 1];
    }
    __syncthreads();

    // ldmatrix base offsets (bytes, pre-swizzle)
    const uint32_t aoffB = (uint32_t)((mwid * 16 + (lane & 15)) * 128 + (lane >> 4) * 16);
    const uint32_t boffB = (uint32_t)((((lane >> 4) & 1) * 8 + (lane & 7)) * 128
                                      + ((lane >> 3) & 1) * 16);

    for (int tile = blockIdx.x; tile < NTILES; tile += gridDim.x) {
        const int n  = tile / MTILES;
        const int mt = tile - n * MTILES;
        const int m0 = mt * TM;
        const float* xn = x + (size_t)n * M_ * FIN_;

        __syncthreads();   // prev tile: smem A reads done before idx/A overwrite
        for (int j = tid; j < TM * K_; j += THREADS) {
            int gi = m0 * K_ + j;
            sIdx[j] = (gi < M_ * K_) ? idx[gi] : 0;
        }
        __syncthreads();

        // ---- COALESCED gather, chunk 0: 16 lanes fetch one 256B x-row ----
        float4 vv[4];
        #pragma unroll
        for (int p = 0; p < 4; p++) {
            const int row = p * 32 + grow;
            const int g = sIdx[row * K_ + 0];
            vv[p] = *(const float4*)(xn + (size_t)g * FIN_ + ql * 4);
        }

        float acc[4][4];
        #pragma unroll
        for (int a = 0; a < 4; a++)
            #pragma unroll
            for (int c = 0; c < 4; c++) acc[a][c] = 0.0f;

        // convert chunk 0 into buf 0
        {
            const uint32_t abase = SA_OFF;
            #pragma unroll
            for (int p = 0; p < 4; p++) {
                const int row = p * 32 + grow;
                float4 a = vv[p];
                uint32_t h0 = bf2(a.x, a.y), h1 = bf2(a.z, a.w);
                uint32_t l0 = bf2(a.x - lowf(h0), a.y - highf(h0));
                uint32_t l1 = bf2(a.z - lowf(h1), a.w - highf(h1));
                const int off = SWZ(row * 128 + ql * 8);   // 8B aligned; SWZ flips bits[6:4] only
                *(uint2*)(smem + abase + off)         = make_uint2(h0, h1);
                *(uint2*)(smem + abase + 16384 + off) = make_uint2(l0, l1);
            }
        }
        __syncthreads();

        for (int k = 0; k < K_; k++) {
            const int b = k & 1;

            // prefetch next chunk's gather (coalesced; hidden under mma below)
            if (k + 1 < K_) {
                #pragma unroll
                for (int p = 0; p < 4; p++) {
                    const int row = p * 32 + grow;
                    const int g = sIdx[row * K_ + (k + 1)];
                    vv[p] = *(const float4*)(xn + (size_t)g * FIN_ + ql * 4);
                }
            }

            // ---- mma chunk k from buf b (this warp: 16 rows x 32 cols) ----
            const uint32_t aHi = sb + SA_OFF + b * 32768;
            const uint32_t aLo = aHi + 16384;
            const uint32_t wHi = sb + SB_OFF + k * 8192;
            const uint32_t wLo = sb + SB_OFF + (K_ + k) * 8192;

            #pragma unroll
            for (int ks = 0; ks < 4; ks++) {
                uint32_t ah[4], al[4];
                ldsm4(ah, aHi + SWZ(aoffB + ks * 32));
                ldsm4(al, aLo + SWZ(aoffB + ks * 32));
                #pragma unroll
                for (int nb = 0; nb < 2; nb++) {
                    uint32_t bh[4], bl[4];
                    const uint32_t bo = boffB + (nh * 2 + nb) * 2048 + ks * 32;
                    ldsm4(bh, wHi + SWZ(bo));
                    ldsm4(bl, wLo + SWZ(bo));
                    mma16816(acc[2 * nb],     ah, bh[0], bh[1]);   // Ah*Wh
                    mma16816(acc[2 * nb + 1], ah, bh[2], bh[3]);
                    mma16816(acc[2 * nb],     ah, bl[0], bl[1]);   // Ah*Wl
                    mma16816(acc[2 * nb + 1], ah, bl[2], bl[3]);
                    mma16816(acc[2 * nb],     al, bh[0], bh[1]);   // Al*Wh
                    mma16816(acc[2 * nb + 1], al, bh[2], bh[3]);
                }
            }

            // ---- convert chunk k+1 into buf b^1 ----
            if (k + 1 < K_) {
                const uint32_t abase = SA_OFF + (b ^ 1) * 32768;
                #pragma unroll
                for (int p = 0; p < 4; p++) {
                    const int row = p * 32 + grow;
                    float4 a = vv[p];
                    uint32_t h0 = bf2(a.x, a.y), h1 = bf2(a.z, a.w);
                    uint32_t l0 = bf2(a.x - lowf(h0), a.y - highf(h0));
                    uint32_t l1 = bf2(a.z - lowf(h1), a.w - highf(h1));
                    const int off = SWZ(row * 128 + ql * 8);
                    *(uint2*)(smem + abase + off)         = make_uint2(h0, h1);
                    *(uint2*)(smem + abase + 16384 + off) = make_uint2(l0, l1);
                }
                __syncthreads();   // buf b^1 ready on all warps
            }
        }

        // ---- epilogue: bias + ELU straight from accumulators ----
        const int row0 = m0 + mwid * 16 + (lane >> 2);
        const int colq = nh * 32 + (lane & 3) * 2;
        #pragma unroll
        for (int ng = 0; ng < 4; ng++) {
            const int col = colq + ng * 8;
            if (row0 < M_) {
                float* d0 = out + ((size_t)n * M_ + row0) * FOUT_ + col;
                float2 o0;
                o0.x = elu1(acc[ng][0] + bb0[ng]);
                o0.y = elu1(acc[ng][1] + bb1[ng]);
                *(float2*)d0 = o0;
            }
            if (row0 + 8 < M_) {
                float* d1 = out + ((size_t)n * M_ + row0 + 8) * FOUT_ + col;
                float2 o1;
                o1.x = elu1(acc[ng][2] + bb0[ng]);
                o1.y = elu1(acc[ng][3] + bb1[ng]);
                *(float2*)d1 = o1;
            }
        }
    }
}

extern "C" void kernel_launch(void* const* d_in, const int* in_sizes, int n_in,
                              void* d_out, int out_size)
{
    const float* x    = (const float*)d_in[0];
    const int*   idx  = (const int*)  d_in[1];
    const float* w    = (const float*)d_in[2];
    const float* bias = (const float*)d_in[3];
    float* out = (float*)d_out;

    (void)in_sizes; (void)n_in; (void)out_size;

    cudaFuncSetAttribute(gconv_mma_kernel,
                         cudaFuncAttributeMaxDynamicSharedMemorySize, SMEM_BYTES);

    prep_w_kernel<<<(WELEMS + 255) / 256, 256>>>(w);
    gconv_mma_kernel<<<NBLOCKS, THREADS, SMEM_BYTES>>>(x, idx, bias, out);
}

// round 11
// speedup vs baseline: 3.4162x; 1.1524x over previous
#include <cuda_runtime.h>
#include <cuda_bf16.h>
#include <math.h>
#include <stdint.h>

// ---------------- problem constants ----------------
#define N_    8
#define M_    50000
#define FIN_  64
#define FOUT_ 64
#define K_    9          // gather fan-in (9 chunks of 64)
#define TM    128        // m rows per tile
#define THREADS 768      // warps 0-15 consumers (mma), warps 16-23 producers (gather+convert)
#define MTILES  ((M_ + TM - 1) / TM)      // 391
#define NTILES  (N_ * MTILES)             // 3128
#define NBLOCKS 148

// ---------------- smem layout (bytes) ----------------
// W (split) : [2 halves][9 chunks][64 rows(o) x 128B] = 147456
// A (split) : [2 bufs][hi 16384 | lo 16384]           =  65536
#define SB_OFF    0
#define SA_OFF    147456
#define SMEM_BYTES 212992

#define SWZ(b) ((b) ^ (((b) >> 3) & 0x70))

// named barriers: full[b] = 1+b, empty[b] = 3+b; count = all 768 threads
#define BAR_SYNC(id)   asm volatile("bar.sync %0, %1;"   :: "r"(id), "r"(THREADS) : "memory")
#define BAR_ARRIVE(id) asm volatile("bar.arrive %0, %1;" :: "r"(id), "r"(THREADS) : "memory")

// ---------------- ptx helpers ----------------
__device__ __forceinline__ uint32_t smem_u32(const void* p) {
    uint32_t a;
    asm("{ .reg .u64 t; cvta.to.shared.u64 t, %1; cvt.u32.u64 %0, t; }" : "=r"(a) : "l"(p));
    return a;
}
__device__ __forceinline__ void ldsm4(uint32_t* r, uint32_t addr) {
    asm volatile("ldmatrix.sync.aligned.m8n8.x4.shared.b16 {%0,%1,%2,%3}, [%4];"
                 : "=r"(r[0]), "=r"(r[1]), "=r"(r[2]), "=r"(r[3]) : "r"(addr));
}
__device__ __forceinline__ void mma16816(float* c, const uint32_t* a, uint32_t b0, uint32_t b1) {
    asm volatile("mma.sync.aligned.m16n8k16.row.col.f32.bf16.bf16.f32 "
                 "{%0,%1,%2,%3},{%4,%5,%6,%7},{%8,%9},{%0,%1,%2,%3};"
                 : "+f"(c[0]), "+f"(c[1]), "+f"(c[2]), "+f"(c[3])
                 : "r"(a[0]), "r"(a[1]), "r"(a[2]), "r"(a[3]), "r"(b0), "r"(b1));
}
// bf16x2 pack: low half = a (lower address), high half = b
__device__ __forceinline__ uint32_t bf2(float a, float b) {
    uint32_t r; asm("cvt.rn.bf16x2.f32 %0, %1, %2;" : "=r"(r) : "f"(b), "f"(a)); return r;
}
__device__ __forceinline__ float lowf(uint32_t p)  { return __uint_as_float(p << 16); }
__device__ __forceinline__ float highf(uint32_t p) { return __uint_as_float(p & 0xFFFF0000u); }
__device__ __forceinline__ float elu1(float v) { return v > 0.0f ? v : expm1f(v); }

// ---------------- weight split scratch: [half][k][o][i] bf16 ----------------
#define WELEMS (K_ * FOUT_ * FIN_)        // 36864
__device__ __nv_bfloat16 g_Wbf[2 * WELEMS];

__global__ void prep_w_kernel(const float* __restrict__ w) {
    int t = blockIdx.x * blockDim.x + threadIdx.x;
    if (t < WELEMS) {
        int k = t >> 12;                  // /4096
        int rr = t & 4095;
        int o = rr >> 6, i = rr & 63;
        float v = w[o * (K_ * FIN_) + k * FIN_ + i];
        __nv_bfloat16 hi = __float2bfloat16_rn(v);
        float lo = v - __bfloat162float(hi);
        g_Wbf[t]          = hi;
        g_Wbf[WELEMS + t] = __float2bfloat16_rn(lo);
    }
}

// ---------------- main kernel ----------------
__global__ __launch_bounds__(THREADS, 1)
void gconv_ws_kernel(const float* __restrict__ x,
                     const int*   __restrict__ idx,
                     const float* __restrict__ bias,
                     float*       __restrict__ out)
{
    extern __shared__ char smem[];
    const uint32_t sb = smem_u32(smem);
    const int tid  = threadIdx.x;
    const int wid  = tid >> 5;
    const int lane = tid & 31;

    // ---- stage split weights into smem with swizzle (once per persistent CTA) ----
    for (int j = tid; j < 2 * K_ * 512; j += THREADS) {     // 16B units
        uint4 v = ((const uint4*)g_Wbf)[j];
        int t8k = j >> 9, u = j & 511;
        *(uint4*)(smem + SB_OFF + t8k * 8192 + SWZ(u * 16)) = v;
    }
    __syncthreads();

    if (wid < 16) {
        // ================= CONSUMERS: pure ldsm + mma + epilogue =================
        const int mwid = wid & 7;          // m-group: rows mwid*16..+16
        const int nh   = wid >> 3;         // n-half: cols nh*32..+32

        float bb0[4], bb1[4];
        #pragma unroll
        for (int ng = 0; ng < 4; ng++) {
            int col = nh * 32 + ng * 8 + (lane & 3) * 2;
            bb0[ng] = bias[col];
            bb1[ng] = bias[col + 1];
        }

        const uint32_t aoffB = (uint32_t)((mwid * 16 + (lane & 15)) * 128 + (lane >> 4) * 16);
        const uint32_t boffB = (uint32_t)((((lane >> 4) & 1) * 8 + (lane & 7)) * 128
                                          + ((lane >> 3) & 1) * 16);
        int c = 0;   // global chunk counter (matches producer's)

        for (int tile = blockIdx.x; tile < NTILES; tile += gridDim.x) {
            const int n  = tile / MTILES;
            const int mt = tile - n * MTILES;
            const int m0 = mt * TM;

            float acc[4][4];
            #pragma unroll
            for (int a = 0; a < 4; a++)
                #pragma unroll
                for (int cc = 0; cc < 4; cc++) acc[a][cc] = 0.0f;

            for (int k = 0; k < K_; k++) {
                const int bsel = c & 1;
                BAR_SYNC(1 + bsel);                      // wait buffer full

                const uint32_t aHi = sb + SA_OFF + bsel * 32768;
                const uint32_t aLo = aHi + 16384;
                const uint32_t wHi = sb + SB_OFF + k * 8192;
                const uint32_t wLo = sb + SB_OFF + (K_ + k) * 8192;

                #pragma unroll
                for (int ks = 0; ks < 4; ks++) {
                    uint32_t ah[4], al[4];
                    ldsm4(ah, aHi + SWZ(aoffB + ks * 32));
                    ldsm4(al, aLo + SWZ(aoffB + ks * 32));
                    #pragma unroll
                    for (int nb = 0; nb < 2; nb++) {
                        uint32_t bh[4], bl[4];
                        const uint32_t bo = boffB + (nh * 2 + nb) * 2048 + ks * 32;
                        ldsm4(bh, wHi + SWZ(bo));
                        ldsm4(bl, wLo + SWZ(bo));
                        mma16816(acc[2 * nb],     ah, bh[0], bh[1]);   // Ah*Wh
                        mma16816(acc[2 * nb + 1], ah, bh[2], bh[3]);
                        mma16816(acc[2 * nb],     ah, bl[0], bl[1]);   // Ah*Wl
                        mma16816(acc[2 * nb + 1], ah, bl[2], bl[3]);
                        mma16816(acc[2 * nb],     al, bh[0], bh[1]);   // Al*Wh
                        mma16816(acc[2 * nb + 1], al, bh[2], bh[3]);
                    }
                }
                BAR_ARRIVE(3 + bsel);                    // buffer free
                c++;
            }

            // ---- epilogue (overlaps with producers filling next tile) ----
            const int row0 = m0 + mwid * 16 + (lane >> 2);
            const int colq = nh * 32 + (lane & 3) * 2;
            #pragma unroll
            for (int ng = 0; ng < 4; ng++) {
                const int col = colq + ng * 8;
                if (row0 < M_) {
                    float* d0 = out + ((size_t)n * M_ + row0) * FOUT_ + col;
                    float2 o0;
                    o0.x = elu1(acc[ng][0] + bb0[ng]);
                    o0.y = elu1(acc[ng][1] + bb1[ng]);
                    *(float2*)d0 = o0;
                }
                if (row0 + 8 < M_) {
                    float* d1 = out + ((size_t)n * M_ + row0 + 8) * FOUT_ + col;
                    float2 o1;
                    o1.x = elu1(acc[ng][2] + bb0[ng]);
                    o1.y = elu1(acc[ng][3] + bb1[ng]);
                    *(float2*)d1 = o1;
                }
            }
        }
    } else {
        // ================= PRODUCERS: gather + bf16 split + STS =================
        const int pt  = tid - 512;         // 0..255
        const int g16 = pt >> 4;           // row group 0..15
        const int ql  = pt & 15;           // 16B slice within row
        int c = 0;

        float4 vv[8];
        int tile = blockIdx.x;

        // prologue: prefetch (tile, chunk 0)
        if (tile < NTILES) {
            const int n  = tile / MTILES;
            const int m0 = (tile - n * MTILES) * TM;
            const float* xn = x + (size_t)n * M_ * FIN_;
            #pragma unroll
            for (int it = 0; it < 8; it++) {
                const int m = m0 + it * 16 + g16;
                const int g = (m < M_) ? idx[m * K_ + 0] : 0;
                vv[it] = *(const float4*)(xn + (size_t)g * FIN_ + ql * 4);
            }
        }

        for (; tile < NTILES; tile += gridDim.x) {
            const int n  = tile / MTILES;
            const int m0 = (tile - n * MTILES) * TM;
            const float* xn = x + (size_t)n * M_ * FIN_;

            for (int k = 0; k < K_; k++) {
                const int bsel = c & 1;
                if (c >= 2) BAR_SYNC(3 + bsel);          // wait buffer free

                // convert vv -> buf bsel (hi + lo)
                const uint32_t abase = SA_OFF + bsel * 32768;
                #pragma unroll
                for (int it = 0; it < 8; it++) {
                    const int row = it * 16 + g16;
                    float4 a = vv[it];
                    uint32_t h0 = bf2(a.x, a.y), h1 = bf2(a.z, a.w);
                    uint32_t l0 = bf2(a.x - lowf(h0), a.y - highf(h0));
                    uint32_t l1 = bf2(a.z - lowf(h1), a.w - highf(h1));
                    const int off = SWZ(row * 128 + ql * 8);
                    *(uint2*)(smem + abase + off)         = make_uint2(h0, h1);
                    *(uint2*)(smem + abase + 16384 + off) = make_uint2(l0, l1);
                }
                BAR_ARRIVE(1 + bsel);                    // buffer full (release)
                c++;

                // prefetch next chunk (this tile k+1, or next tile chunk 0)
                if (k + 1 < K_) {
                    #pragma unroll
                    for (int it = 0; it < 8; it++) {
                        const int m = m0 + it * 16 + g16;
                        const int g = (m < M_) ? idx[m * K_ + (k + 1)] : 0;
                        vv[it] = *(const float4*)(xn + (size_t)g * FIN_ + ql * 4);
                    }
                } else {
                    const int t2 = tile + gridDim.x;
                    if (t2 < NTILES) {
                        const int n2  = t2 / MTILES;
                        const int m02 = (t2 - n2 * MTILES) * TM;
                        const float* xn2 = x + (size_t)n2 * M_ * FIN_;
                        #pragma unroll
                        for (int it = 0; it < 8; it++) {
                            const int m = m02 + it * 16 + g16;
                            const int g = (m < M_) ? idx[m * K_ + 0] : 0;
                            vv[it] = *(const float4*)(xn2 + (size_t)g * FIN_ + ql * 4);
                        }
                    }
                }
            }
        }
    }
}

extern "C" void kernel_launch(void* const* d_in, const int* in_sizes, int n_in,
                              void* d_out, int out_size)
{
    const float* x    = (const float*)d_in[0];
    const int*   idx  = (const int*)  d_in[1];
    const float* w    = (const float*)d_in[2];
    const float* bias = (const float*)d_in[3];
    float* out = (float*)d_out;

    (void)in_sizes; (void)n_in; (void)out_size;

    cudaFuncSetAttribute(gconv_ws_kernel,
                         cudaFuncAttributeMaxDynamicSharedMemorySize, SMEM_BYTES);

    prep_w_kernel<<<(WELEMS + 255) / 256, 256>>>(w);
    gconv_ws_kernel<<<NBLOCKS, THREADS, SMEM_BYTES>>>(x, idx, bias, out);
}

// round 12
// speedup vs baseline: 3.4740x; 1.0169x over previous
#include <cuda_runtime.h>
#include <cuda_bf16.h>
#include <math.h>
#include <stdint.h>

// ---------------- problem constants ----------------
#define N_    8
#define M_    50000
#define FIN_  64
#define FOUT_ 64
#define K_    9          // gather fan-in (9 chunks of 64)
#define TM    128        // m rows per tile
#define THREADS 512      // warps 0-7 consumers (32x32 mma tiles), warps 8-15 producers
#define MTILES  ((M_ + TM - 1) / TM)      // 391
#define NTILES  (N_ * MTILES)             // 3128
#define NBLOCKS 148

// ---------------- smem layout (bytes) ----------------
// W (split) : [2 halves][9 chunks][64 rows(o) x 128B] = 147456
// A (split) : [2 bufs][hi 16384 | lo 16384]           =  65536
#define SB_OFF    0
#define SA_OFF    147456
#define SMEM_BYTES 212992

#define SWZ(b) ((b) ^ (((b) >> 3) & 0x70))

// named barriers: full[b] = 1+b, empty[b] = 3+b; count = all 512 threads
#define BAR_SYNC(id)   asm volatile("bar.sync %0, %1;"   :: "r"(id), "r"(THREADS) : "memory")
#define BAR_ARRIVE(id) asm volatile("bar.arrive %0, %1;" :: "r"(id), "r"(THREADS) : "memory")

// ---------------- ptx helpers ----------------
__device__ __forceinline__ uint32_t smem_u32(const void* p) {
    uint32_t a;
    asm("{ .reg .u64 t; cvta.to.shared.u64 t, %1; cvt.u32.u64 %0, t; }" : "=r"(a) : "l"(p));
    return a;
}
__device__ __forceinline__ void ldsm4(uint32_t* r, uint32_t addr) {
    asm volatile("ldmatrix.sync.aligned.m8n8.x4.shared.b16 {%0,%1,%2,%3}, [%4];"
                 : "=r"(r[0]), "=r"(r[1]), "=r"(r[2]), "=r"(r[3]) : "r"(addr));
}
__device__ __forceinline__ void mma16816(float* c, const uint32_t* a, uint32_t b0, uint32_t b1) {
    asm volatile("mma.sync.aligned.m16n8k16.row.col.f32.bf16.bf16.f32 "
                 "{%0,%1,%2,%3},{%4,%5,%6,%7},{%8,%9},{%0,%1,%2,%3};"
                 : "+f"(c[0]), "+f"(c[1]), "+f"(c[2]), "+f"(c[3])
                 : "r"(a[0]), "r"(a[1]), "r"(a[2]), "r"(a[3]), "r"(b0), "r"(b1));
}
// bf16x2 pack: low half = a (lower address), high half = b
__device__ __forceinline__ uint32_t bf2(float a, float b) {
    uint32_t r; asm("cvt.rn.bf16x2.f32 %0, %1, %2;" : "=r"(r) : "f"(b), "f"(a)); return r;
}
__device__ __forceinline__ float lowf(uint32_t p)  { return __uint_as_float(p << 16); }
__device__ __forceinline__ float highf(uint32_t p) { return __uint_as_float(p & 0xFFFF0000u); }
__device__ __forceinline__ float elu1(float v) { return v > 0.0f ? v : expm1f(v); }

// ---------------- weight split scratch: [half][k][o][i] bf16 ----------------
#define WELEMS (K_ * FOUT_ * FIN_)        // 36864
__device__ __nv_bfloat16 g_Wbf[2 * WELEMS];

__global__ void prep_w_kernel(const float* __restrict__ w) {
    int t = blockIdx.x * blockDim.x + threadIdx.x;
    if (t < WELEMS) {
        int k = t >> 12;                  // /4096
        int rr = t & 4095;
        int o = rr >> 6, i = rr & 63;
        float v = w[o * (K_ * FIN_) + k * FIN_ + i];
        __nv_bfloat16 hi = __float2bfloat16_rn(v);
        float lo = v - __bfloat162float(hi);
        g_Wbf[t]          = hi;
        g_Wbf[WELEMS + t] = __float2bfloat16_rn(lo);
    }
}

// ---------------- main kernel ----------------
__global__ __launch_bounds__(THREADS, 1)
void gconv_ws_kernel(const float* __restrict__ x,
                     const int*   __restrict__ idx,
                     const float* __restrict__ bias,
                     float*       __restrict__ out)
{
    extern __shared__ char smem[];
    const uint32_t sb = smem_u32(smem);
    const int tid  = threadIdx.x;
    const int wid  = tid >> 5;
    const int lane = tid & 31;

    // ---- stage split weights into smem with swizzle (once per persistent CTA) ----
    for (int j = tid; j < 2 * K_ * 512; j += THREADS) {     // 16B units
        uint4 v = ((const uint4*)g_Wbf)[j];
        int t8k = j >> 9, u = j & 511;
        *(uint4*)(smem + SB_OFF + t8k * 8192 + SWZ(u * 16)) = v;
    }
    __syncthreads();

    if (wid < 8) {
        // ======== CONSUMERS: 32m x 32n warp tiles, pure ldsm + mma + epilogue ========
        const int mwid = wid & 3;          // m-group: rows mwid*32..+32
        const int nh   = wid >> 2;         // n-half: cols nh*32..+32

        float bb0[4], bb1[4];
        #pragma unroll
        for (int ng = 0; ng < 4; ng++) {
            int col = nh * 32 + ng * 8 + (lane & 3) * 2;
            bb0[ng] = bias[col];
            bb1[ng] = bias[col + 1];
        }

        // ldmatrix base offsets (bytes, pre-swizzle); ms = m16 sub-tile 0/1
        const uint32_t aoff0 = (uint32_t)((mwid * 32 + (lane & 15)) * 128 + (lane >> 4) * 16);
        const uint32_t aoff1 = aoff0 + 16 * 128;
        const uint32_t boffB = (uint32_t)((((lane >> 4) & 1) * 8 + (lane & 7)) * 128
                                          + ((lane >> 3) & 1) * 16);
        int c = 0;   // global chunk counter (matches producer's)

        for (int tile = blockIdx.x; tile < NTILES; tile += gridDim.x) {
            const int n  = tile / MTILES;
            const int mt = tile - n * MTILES;
            const int m0 = mt * TM;

            float acc[2][4][4];
            #pragma unroll
            for (int ms = 0; ms < 2; ms++)
                #pragma unroll
                for (int a = 0; a < 4; a++)
                    #pragma unroll
                    for (int cc = 0; cc < 4; cc++) acc[ms][a][cc] = 0.0f;

            for (int k = 0; k < K_; k++) {
                const int bsel = c & 1;
                BAR_SYNC(1 + bsel);                      // wait buffer full

                const uint32_t aHi = sb + SA_OFF + bsel * 32768;
                const uint32_t aLo = aHi + 16384;
                const uint32_t wHi = sb + SB_OFF + k * 8192;
                const uint32_t wLo = sb + SB_OFF + (K_ + k) * 8192;

                #pragma unroll
                for (int ks = 0; ks < 4; ks++) {
                    uint32_t ah0[4], ah1[4], al0[4], al1[4];
                    ldsm4(ah0, aHi + SWZ(aoff0 + ks * 32));
                    ldsm4(ah1, aHi + SWZ(aoff1 + ks * 32));
                    ldsm4(al0, aLo + SWZ(aoff0 + ks * 32));
                    ldsm4(al1, aLo + SWZ(aoff1 + ks * 32));
                    #pragma unroll
                    for (int nb = 0; nb < 2; nb++) {
                        uint32_t bh[4], bl[4];
                        const uint32_t bo = boffB + (nh * 2 + nb) * 2048 + ks * 32;
                        ldsm4(bh, wHi + SWZ(bo));
                        ldsm4(bl, wLo + SWZ(bo));
                        float* c00 = acc[0][2 * nb];
                        float* c01 = acc[0][2 * nb + 1];
                        float* c10 = acc[1][2 * nb];
                        float* c11 = acc[1][2 * nb + 1];
                        mma16816(c00, ah0, bh[0], bh[1]);   // Ah*Wh
                        mma16816(c01, ah0, bh[2], bh[3]);
                        mma16816(c10, ah1, bh[0], bh[1]);
                        mma16816(c11, ah1, bh[2], bh[3]);
                        mma16816(c00, ah0, bl[0], bl[1]);   // Ah*Wl
                        mma16816(c01, ah0, bl[2], bl[3]);
                        mma16816(c10, ah1, bl[0], bl[1]);
                        mma16816(c11, ah1, bl[2], bl[3]);
                        mma16816(c00, al0, bh[0], bh[1]);   // Al*Wh
                        mma16816(c01, al0, bh[2], bh[3]);
                        mma16816(c10, al1, bh[0], bh[1]);
                        mma16816(c11, al1, bh[2], bh[3]);
                    }
                }
                BAR_ARRIVE(3 + bsel);                    // buffer free
                c++;
            }

            // ---- epilogue (overlaps with producers filling next tile) ----
            const int colq = nh * 32 + (lane & 3) * 2;
            #pragma unroll
            for (int ms = 0; ms < 2; ms++) {
                const int row0 = m0 + mwid * 32 + ms * 16 + (lane >> 2);
                #pragma unroll
                for (int ng = 0; ng < 4; ng++) {
                    const int col = colq + ng * 8;
                    if (row0 < M_) {
                        float* d0 = out + ((size_t)n * M_ + row0) * FOUT_ + col;
                        float2 o0;
                        o0.x = elu1(acc[ms][ng][0] + bb0[ng]);
                        o0.y = elu1(acc[ms][ng][1] + bb1[ng]);
                        *(float2*)d0 = o0;
                    }
                    if (row0 + 8 < M_) {
                        float* d1 = out + ((size_t)n * M_ + row0 + 8) * FOUT_ + col;
                        float2 o1;
                        o1.x = elu1(acc[ms][ng][2] + bb0[ng]);
                        o1.y = elu1(acc[ms][ng][3] + bb1[ng]);
                        *(float2*)d1 = o1;
                    }
                }
            }
        }
    } else {
        // ================= PRODUCERS: gather + bf16 split + STS =================
        const int pt  = tid - 256;         // 0..255
        const int g16 = pt >> 4;           // row group 0..15
        const int ql  = pt & 15;           // 16B slice within row
        int c = 0;

        float4 vv[8];
        int tile = blockIdx.x;

        // prologue: prefetch (tile, chunk 0)
        if (tile < NTILES) {
            const int n  = tile / MTILES;
            const int m0 = (tile - n * MTILES) * TM;
            const float* xn = x + (size_t)n * M_ * FIN_;
            #pragma unroll
            for (int it = 0; it < 8; it++) {
                const int m = m0 + it * 16 + g16;
                const int g = (m < M_) ? idx[m * K_ + 0] : 0;
                vv[it] = *(const float4*)(xn + (size_t)g * FIN_ + ql * 4);
            }
        }

        for (; tile < NTILES; tile += gridDim.x) {
            const int n  = tile / MTILES;
            const int m0 = (tile - n * MTILES) * TM;
            const float* xn = x + (size_t)n * M_ * FIN_;

            for (int k = 0; k < K_; k++) {
                const int bsel = c & 1;
                if (c >= 2) BAR_SYNC(3 + bsel);          // wait buffer free

                // convert vv -> buf bsel (hi + lo)
                const uint32_t abase = SA_OFF + bsel * 32768;
                #pragma unroll
                for (int it = 0; it < 8; it++) {
                    const int row = it * 16 + g16;
                    float4 a = vv[it];
                    uint32_t h0 = bf2(a.x, a.y), h1 = bf2(a.z, a.w);
                    uint32_t l0 = bf2(a.x - lowf(h0), a.y - highf(h0));
                    uint32_t l1 = bf2(a.z - lowf(h1), a.w - highf(h1));
                    const int off = SWZ(row * 128 + ql * 8);
                    *(uint2*)(smem + abase + off)         = make_uint2(h0, h1);
                    *(uint2*)(smem + abase + 16384 + off) = make_uint2(l0, l1);
                }
                BAR_ARRIVE(1 + bsel);                    // buffer full (release)
                c++;

                // prefetch next chunk (this tile k+1, or next tile chunk 0)
                if (k + 1 < K_) {
                    #pragma unroll
                    for (int it = 0; it < 8; it++) {
                        const int m = m0 + it * 16 + g16;
                        const int g = (m < M_) ? idx[m * K_ + (k + 1)] : 0;
                        vv[it] = *(const float4*)(xn + (size_t)g * FIN_ + ql * 4);
                    }
                } else {
                    const int t2 = tile + gridDim.x;
                    if (t2 < NTILES) {
                        const int n2  = t2 / MTILES;
                        const int m02 = (t2 - n2 * MTILES) * TM;
                        const float* xn2 = x + (size_t)n2 * M_ * FIN_;
                        #pragma unroll
                        for (int it = 0; it < 8; it++) {
                            const int m = m02 + it * 16 + g16;
                            const int g = (m < M_) ? idx[m * K_ + 0] : 0;
                            vv[it] = *(const float4*)(xn2 + (size_t)g * FIN_ + ql * 4);
                        }
                    }
                }
            }
        }
    }
}

extern "C" void kernel_launch(void* const* d_in, const int* in_sizes, int n_in,
                              void* d_out, int out_size)
{
    const float* x    = (const float*)d_in[0];
    const int*   idx  = (const int*)  d_in[1];
    const float* w    = (const float*)d_in[2];
    const float* bias = (const float*)d_in[3];
    float* out = (float*)d_out;

    (void)in_sizes; (void)n_in; (void)out_size;

    cudaFuncSetAttribute(gconv_ws_kernel,
                         cudaFuncAttributeMaxDynamicSharedMemorySize, SMEM_BYTES);

    prep_w_kernel<<<(WELEMS + 255) / 256, 256>>>(w);
    gconv_ws_kernel<<<NBLOCKS, THREADS, SMEM_BYTES>>>(x, idx, bias, out);
}

// round 13
// speedup vs baseline: 4.2654x; 1.2278x over previous
#include <cuda_runtime.h>
#include <cuda_fp16.h>
#include <math.h>
#include <stdint.h>

// ---------------- problem constants ----------------
#define N_    8
#define M_    50000
#define FIN_  64
#define FOUT_ 64
#define K_    9          // gather fan-in (9 chunks of 64)
#define TM    128        // m rows per tile
#define THREADS 512      // warps 0-7 consumers (32x32 tiles), warps 8-15 producers
#define MTILES  ((M_ + TM - 1) / TM)      // 391
#define NTILES  (N_ * MTILES)             // 3128
#define NBLOCKS 148

// ---------------- smem layout (bytes) ----------------
// W (fp16 split) : [2 halves][9 chunks][64 o x 128B] = 147456
// A (fp16)       : [3 bufs][128 rows x 128B]         =  49152
#define SB_OFF    0
#define SA_OFF    147456
#define SMEM_BYTES 196608

#define SWZ(b) ((b) ^ (((b) >> 3) & 0x70))

// named barriers: full[s] = 1+s, empty[s] = 4+s (s=0..2); count = all 512 threads
#define BAR_SYNC(id)   asm volatile("bar.sync %0, %1;"   :: "r"(id), "r"(THREADS) : "memory")
#define BAR_ARRIVE(id) asm volatile("bar.arrive %0, %1;" :: "r"(id), "r"(THREADS) : "memory")

// ---------------- ptx helpers ----------------
__device__ __forceinline__ uint32_t smem_u32(const void* p) {
    uint32_t a;
    asm("{ .reg .u64 t; cvta.to.shared.u64 t, %1; cvt.u32.u64 %0, t; }" : "=r"(a) : "l"(p));
    return a;
}
__device__ __forceinline__ void ldsm4(uint32_t* r, uint32_t addr) {
    asm volatile("ldmatrix.sync.aligned.m8n8.x4.shared.b16 {%0,%1,%2,%3}, [%4];"
                 : "=r"(r[0]), "=r"(r[1]), "=r"(r[2]), "=r"(r[3]) : "r"(addr));
}
__device__ __forceinline__ void mma16816(float* c, const uint32_t* a, uint32_t b0, uint32_t b1) {
    asm volatile("mma.sync.aligned.m16n8k16.row.col.f32.f16.f16.f32 "
                 "{%0,%1,%2,%3},{%4,%5,%6,%7},{%8,%9},{%0,%1,%2,%3};"
                 : "+f"(c[0]), "+f"(c[1]), "+f"(c[2]), "+f"(c[3])
                 : "r"(a[0]), "r"(a[1]), "r"(a[2]), "r"(a[3]), "r"(b0), "r"(b1));
}
// fp16x2 pack: low half = a (lower address), high half = b
__device__ __forceinline__ uint32_t f16p(float a, float b) {
    uint32_t r; asm("cvt.rn.f16x2.f32 %0, %1, %2;" : "=r"(r) : "f"(b), "f"(a)); return r;
}
__device__ __forceinline__ float elu1(float v) { return v > 0.0f ? v : expm1f(v); }

// ---------------- weight split scratch: [half][k][o][i] fp16 ----------------
#define WELEMS (K_ * FOUT_ * FIN_)        // 36864
__device__ __half g_Whf[2 * WELEMS];

__global__ void prep_w_kernel(const float* __restrict__ w) {
    int t = blockIdx.x * blockDim.x + threadIdx.x;
    if (t < WELEMS) {
        int k = t >> 12;                  // /4096
        int rr = t & 4095;
        int o = rr >> 6, i = rr & 63;
        float v = w[o * (K_ * FIN_) + k * FIN_ + i];
        __half hi = __float2half_rn(v);
        float lo = v - __half2float(hi);
        g_Whf[t]          = hi;
        g_Whf[WELEMS + t] = __float2half_rn(lo);
    }
}

// ---------------- main kernel ----------------
__global__ __launch_bounds__(THREADS, 1)
void gconv_ws_kernel(const float* __restrict__ x,
                     const int*   __restrict__ idx,
                     const float* __restrict__ bias,
                     float*       __restrict__ out)
{
    extern __shared__ char smem[];
    const uint32_t sb = smem_u32(smem);
    const int tid  = threadIdx.x;
    const int wid  = tid >> 5;
    const int lane = tid & 31;

    // ---- stage split weights into smem with swizzle (once per persistent CTA) ----
    for (int j = tid; j < 2 * K_ * 512; j += THREADS) {     // 16B units
        uint4 v = ((const uint4*)g_Whf)[j];
        int t8k = j >> 9, u = j & 511;
        *(uint4*)(smem + SB_OFF + t8k * 8192 + SWZ(u * 16)) = v;
    }
    __syncthreads();

    if (wid < 8) {
        // ======== CONSUMERS: 32m x 32n warp tiles, pipelined ldsm + mma ========
        const int mwid = wid & 3;          // m-group: rows mwid*32..+32
        const int nh   = wid >> 2;         // n-half: cols nh*32..+32

        float bb0[4], bb1[4];
        #pragma unroll
        for (int ng = 0; ng < 4; ng++) {
            int col = nh * 32 + ng * 8 + (lane & 3) * 2;
            bb0[ng] = bias[col];
            bb1[ng] = bias[col + 1];
        }

        // hoisted swizzled offsets (k-invariant; all larger strides are additive-safe)
        const uint32_t aoff0 = (uint32_t)((mwid * 32 + (lane & 15)) * 128 + (lane >> 4) * 16);
        const uint32_t boff0 = (uint32_t)((((lane >> 4) & 1) * 8 + (lane & 7)) * 128
                                          + ((lane >> 3) & 1) * 16);
        uint32_t swzA[4], swzB[4];
        #pragma unroll
        for (int ks = 0; ks < 4; ks++) {
            swzA[ks] = SWZ(aoff0 + ks * 32);
            swzB[ks] = SWZ(boff0 + ks * 32);
        }
        int c = 0;   // global chunk counter (matches producer's)

        for (int tile = blockIdx.x; tile < NTILES; tile += gridDim.x) {
            const int n  = tile / MTILES;
            const int mt = tile - n * MTILES;
            const int m0 = mt * TM;

            float acc[2][4][4];
            #pragma unroll
            for (int ms = 0; ms < 2; ms++)
                #pragma unroll
                for (int a = 0; a < 4; a++)
                    #pragma unroll
                    for (int cc = 0; cc < 4; cc++) acc[ms][a][cc] = 0.0f;

            for (int k = 0; k < K_; k++) {
                const int s = c % 3;
                BAR_SYNC(1 + s);                         // wait buffer full

                const uint32_t aBase = sb + SA_OFF + s * 16384;
                const uint32_t wH = sb + SB_OFF + k * 8192 + nh * 4096;
                const uint32_t wL = wH + K_ * 8192;

                uint32_t af[2][8], bf[2][16];
                // preload ks=0 fragments
                ldsm4(af[0] + 0,  aBase + swzA[0]);
                ldsm4(af[0] + 4,  aBase + swzA[0] + 2048);
                ldsm4(bf[0] + 0,  wH + swzB[0]);
                ldsm4(bf[0] + 4,  wL + swzB[0]);
                ldsm4(bf[0] + 8,  wH + swzB[0] + 2048);
                ldsm4(bf[0] + 12, wL + swzB[0] + 2048);

                #pragma unroll
                for (int ks = 0; ks < 4; ks++) {
                    const int cur = ks & 1, nxt = cur ^ 1;
                    if (ks < 3) {                        // prefetch ks+1 under mma
                        ldsm4(af[nxt] + 0,  aBase + swzA[ks + 1]);
                        ldsm4(af[nxt] + 4,  aBase + swzA[ks + 1] + 2048);
                        ldsm4(bf[nxt] + 0,  wH + swzB[ks + 1]);
                        ldsm4(bf[nxt] + 4,  wL + swzB[ks + 1]);
                        ldsm4(bf[nxt] + 8,  wH + swzB[ks + 1] + 2048);
                        ldsm4(bf[nxt] + 12, wL + swzB[ks + 1] + 2048);
                    }
                    #pragma unroll
                    for (int nb = 0; nb < 2; nb++) {
                        const uint32_t* a0 = af[cur];
                        const uint32_t* a1 = af[cur] + 4;
                        const uint32_t* bh = bf[cur] + nb * 8;
                        const uint32_t* bl = bh + 4;
                        float* c00 = acc[0][2 * nb];
                        float* c01 = acc[0][2 * nb + 1];
                        float* c10 = acc[1][2 * nb];
                        float* c11 = acc[1][2 * nb + 1];
                        mma16816(c00, a0, bh[0], bh[1]);   // A*Wh
                        mma16816(c01, a0, bh[2], bh[3]);
                        mma16816(c10, a1, bh[0], bh[1]);
                        mma16816(c11, a1, bh[2], bh[3]);
                        mma16816(c00, a0, bl[0], bl[1]);   // A*Wl
                        mma16816(c01, a0, bl[2], bl[3]);
                        mma16816(c10, a1, bl[0], bl[1]);
                        mma16816(c11, a1, bl[2], bl[3]);
                    }
                }
                BAR_ARRIVE(4 + s);                       // buffer free
                c++;
            }

            // ---- epilogue (overlaps with producers running ahead) ----
            const int colq = nh * 32 + (lane & 3) * 2;
            #pragma unroll
            for (int ms = 0; ms < 2; ms++) {
                const int row0 = m0 + mwid * 32 + ms * 16 + (lane >> 2);
                #pragma unroll
                for (int ng = 0; ng < 4; ng++) {
                    const int col = colq + ng * 8;
                    if (row0 < M_) {
                        float* d0 = out + ((size_t)n * M_ + row0) * FOUT_ + col;
                        float2 o0;
                        o0.x = elu1(acc[ms][ng][0] + bb0[ng]);
                        o0.y = elu1(acc[ms][ng][1] + bb1[ng]);
                        *(float2*)d0 = o0;
                    }
                    if (row0 + 8 < M_) {
                        float* d1 = out + ((size_t)n * M_ + row0 + 8) * FOUT_ + col;
                        float2 o1;
                        o1.x = elu1(acc[ms][ng][2] + bb0[ng]);
                        o1.y = elu1(acc[ms][ng][3] + bb1[ng]);
                        *(float2*)d1 = o1;
                    }
                }
            }
        }
    } else {
        // ============== PRODUCERS: gather + fp16 convert + STS ==============
        const int pt  = tid - 256;         // 0..255
        const int g16 = pt >> 4;           // row group 0..15
        const int ql  = pt & 15;           // 16B gather slice / 8B store slice
        uint32_t soff[8];
        #pragma unroll
        for (int it = 0; it < 8; it++)
            soff[it] = SWZ((uint32_t)((it * 16 + g16) * 128 + ql * 8));
        int c = 0;

        float4 vv[8];
        int tile = blockIdx.x;

        // prologue: prefetch (tile, chunk 0)
        if (tile < NTILES) {
            const int n  = tile / MTILES;
            const int m0 = (tile - n * MTILES) * TM;
            const float* xn = x + (size_t)n * M_ * FIN_;
            #pragma unroll
            for (int it = 0; it < 8; it++) {
                const int m = m0 + it * 16 + g16;
                const int g = (m < M_) ? idx[m * K_ + 0] : 0;
                vv[it] = *(const float4*)(xn + (size_t)g * FIN_ + ql * 4);
            }
        }

        for (; tile < NTILES; tile += gridDim.x) {
            const int n  = tile / MTILES;
            const int m0 = (tile - n * MTILES) * TM;
            const float* xn = x + (size_t)n * M_ * FIN_;

            for (int k = 0; k < K_; k++) {
                const int s = c % 3;
                if (c >= 3) BAR_SYNC(4 + s);             // wait buffer free

                // convert vv -> fp16 buf s
                const uint32_t abase = SA_OFF + s * 16384;
                #pragma unroll
                for (int it = 0; it < 8; it++) {
                    float4 a = vv[it];
                    uint32_t h0 = f16p(a.x, a.y), h1 = f16p(a.z, a.w);
                    *(uint2*)(smem + abase + soff[it]) = make_uint2(h0, h1);
                }
                BAR_ARRIVE(1 + s);                       // buffer full (release)
                c++;

                // prefetch next chunk (this tile k+1, or next tile chunk 0)
                if (k + 1 < K_) {
                    #pragma unroll
                    for (int it = 0; it < 8; it++) {
                        const int m = m0 + it * 16 + g16;
                        const int g = (m < M_) ? idx[m * K_ + (k + 1)] : 0;
                        vv[it] = *(const float4*)(xn + (size_t)g * FIN_ + ql * 4);
                    }
                } else {
                    const int t2 = tile + gridDim.x;
                    if (t2 < NTILES) {
                        const int n2  = t2 / MTILES;
                        const int m02 = (t2 - n2 * MTILES) * TM;
                        const float* xn2 = x + (size_t)n2 * M_ * FIN_;
                        #pragma unroll
                        for (int it = 0; it < 8; it++) {
                            const int m = m02 + it * 16 + g16;
                            const int g = (m < M_) ? idx[m * K_ + 0] : 0;
                            vv[it] = *(const float4*)(xn2 + (size_t)g * FIN_ + ql * 4);
                        }
                    }
                }
            }
        }
    }
}

extern "C" void kernel_launch(void* const* d_in, const int* in_sizes, int n_in,
                              void* d_out, int out_size)
{
    const float* x    = (const float*)d_in[0];
    const int*   idx  = (const int*)  d_in[1];
    const float* w    = (const float*)d_in[2];
    const float* bias = (const float*)d_in[3];
    float* out = (float*)d_out;

    (void)in_sizes; (void)n_in; (void)out_size;

    cudaFuncSetAttribute(gconv_ws_kernel,
                         cudaFuncAttributeMaxDynamicSharedMemorySize, SMEM_BYTES);

    prep_w_kernel<<<(WELEMS + 255) / 256, 256>>>(w);
    gconv_ws_kernel<<<NBLOCKS, THREADS, SMEM_BYTES>>>(x, idx, bias, out);
}

// round 14
// speedup vs baseline: 4.6636x; 1.0934x over previous
#include <cuda_runtime.h>
#include <cuda_fp16.h>
#include <math.h>
#include <stdint.h>

// ---------------- problem constants ----------------
#define N_    8
#define M_    50000
#define FIN_  64
#define FOUT_ 64
#define K_    9          // gather fan-in (9 chunks of 64)
#define TM    64         // m rows per tile (small tile -> 2 CTAs/SM)
#define THREADS 256      // warps 0-3 consumers (32x32 tiles), warps 4-7 producers
#define MTILES  ((M_ + TM - 1) / TM)      // 782
#define NTILES  (N_ * MTILES)             // 6256
#define NBLOCKS 296                       // 2 persistent CTAs per SM

// ---------------- smem layout (bytes, per CTA) ----------------
// W (fp16) : [9 chunks][64 o x 128B] = 73728
// A (fp16) : [2 bufs][64 rows x 128B] = 16384
#define SB_OFF    0
#define SA_OFF    73728
#define SMEM_BYTES 90112

#define SWZ(b) ((b) ^ (((b) >> 3) & 0x70))

// named barriers: full[b] = 1+b, empty[b] = 3+b; count = all 256 threads
#define BAR_SYNC(id)   asm volatile("bar.sync %0, %1;"   :: "r"(id), "r"(THREADS) : "memory")
#define BAR_ARRIVE(id) asm volatile("bar.arrive %0, %1;" :: "r"(id), "r"(THREADS) : "memory")

// ---------------- ptx helpers ----------------
__device__ __forceinline__ uint32_t smem_u32(const void* p) {
    uint32_t a;
    asm("{ .reg .u64 t; cvta.to.shared.u64 t, %1; cvt.u32.u64 %0, t; }" : "=r"(a) : "l"(p));
    return a;
}
__device__ __forceinline__ void ldsm4(uint32_t* r, uint32_t addr) {
    asm volatile("ldmatrix.sync.aligned.m8n8.x4.shared.b16 {%0,%1,%2,%3}, [%4];"
                 : "=r"(r[0]), "=r"(r[1]), "=r"(r[2]), "=r"(r[3]) : "r"(addr));
}
__device__ __forceinline__ void mma16816(float* c, const uint32_t* a, uint32_t b0, uint32_t b1) {
    asm volatile("mma.sync.aligned.m16n8k16.row.col.f32.f16.f16.f32 "
                 "{%0,%1,%2,%3},{%4,%5,%6,%7},{%8,%9},{%0,%1,%2,%3};"
                 : "+f"(c[0]), "+f"(c[1]), "+f"(c[2]), "+f"(c[3])
                 : "r"(a[0]), "r"(a[1]), "r"(a[2]), "r"(a[3]), "r"(b0), "r"(b1));
}
// fp16x2 pack: low half = a (lower address), high half = b
__device__ __forceinline__ uint32_t f16p(float a, float b) {
    uint32_t r; asm("cvt.rn.f16x2.f32 %0, %1, %2;" : "=r"(r) : "f"(b), "f"(a)); return r;
}
__device__ __forceinline__ float elu1(float v) { return v > 0.0f ? v : expm1f(v); }

// ---------------- weight fp16 scratch: [k][o][i] ----------------
#define WELEMS (K_ * FOUT_ * FIN_)        // 36864
__device__ __half g_Whf[WELEMS];

__global__ void prep_w_kernel(const float* __restrict__ w) {
    int t = blockIdx.x * blockDim.x + threadIdx.x;
    if (t < WELEMS) {
        int k = t >> 12;                  // /4096
        int rr = t & 4095;
        int o = rr >> 6, i = rr & 63;
        g_Whf[t] = __float2half_rn(w[o * (K_ * FIN_) + k * FIN_ + i]);
    }
}

// ---------------- main kernel ----------------
__global__ __launch_bounds__(THREADS, 2)
void gconv_ws_kernel(const float* __restrict__ x,
                     const int*   __restrict__ idx,
                     const float* __restrict__ bias,
                     float*       __restrict__ out)
{
    extern __shared__ char smem[];
    const uint32_t sb = smem_u32(smem);
    const int tid  = threadIdx.x;
    const int wid  = tid >> 5;
    const int lane = tid & 31;

    // ---- stage fp16 weights into smem with swizzle (once per persistent CTA) ----
    for (int j = tid; j < K_ * 512; j += THREADS) {          // 16B units
        uint4 v = ((const uint4*)g_Whf)[j];
        int t8k = j >> 9, u = j & 511;
        *(uint4*)(smem + SB_OFF + t8k * 8192 + SWZ(u * 16)) = v;
    }
    __syncthreads();

    if (wid < 4) {
        // ======== CONSUMERS: 32m x 32n warp tiles, pipelined ldsm + mma ========
        const int mwid = wid & 1;          // m-group: rows mwid*32..+32
        const int nh   = wid >> 1;         // n-half: cols nh*32..+32

        float bb0[4], bb1[4];
        #pragma unroll
        for (int ng = 0; ng < 4; ng++) {
            int col = nh * 32 + ng * 8 + (lane & 3) * 2;
            bb0[ng] = bias[col];
            bb1[ng] = bias[col + 1];
        }

        // hoisted swizzled offsets (k-invariant)
        const uint32_t aoff0 = (uint32_t)((mwid * 32 + (lane & 15)) * 128 + (lane >> 4) * 16);
        const uint32_t boff0 = (uint32_t)((((lane >> 4) & 1) * 8 + (lane & 7)) * 128
                                          + ((lane >> 3) & 1) * 16);
        uint32_t swzA[4], swzB[4];
        #pragma unroll
        for (int ks = 0; ks < 4; ks++) {
            swzA[ks] = SWZ(aoff0 + ks * 32);
            swzB[ks] = SWZ(boff0 + ks * 32);
        }
        int c = 0;   // global chunk counter (matches producer's)

        for (int tile = blockIdx.x; tile < NTILES; tile += gridDim.x) {
            const int n  = tile / MTILES;
            const int mt = tile - n * MTILES;
            const int m0 = mt * TM;

            float acc[2][4][4];
            #pragma unroll
            for (int ms = 0; ms < 2; ms++)
                #pragma unroll
                for (int a = 0; a < 4; a++)
                    #pragma unroll
                    for (int cc = 0; cc < 4; cc++) acc[ms][a][cc] = 0.0f;

            for (int k = 0; k < K_; k++) {
                const int bsel = c & 1;
                BAR_SYNC(1 + bsel);                      // wait buffer full

                const uint32_t aBase = sb + SA_OFF + bsel * 8192;
                const uint32_t wH = sb + SB_OFF + k * 8192 + nh * 4096;

                uint32_t af[2][8], bf[2][8];
                // preload ks=0 fragments
                ldsm4(af[0] + 0, aBase + swzA[0]);
                ldsm4(af[0] + 4, aBase + swzA[0] + 2048);
                ldsm4(bf[0] + 0, wH + swzB[0]);
                ldsm4(bf[0] + 4, wH + swzB[0] + 2048);

                #pragma unroll
                for (int ks = 0; ks < 4; ks++) {
                    const int cur = ks & 1, nxt = cur ^ 1;
                    if (ks < 3) {                        // prefetch ks+1 under mma
                        ldsm4(af[nxt] + 0, aBase + swzA[ks + 1]);
                        ldsm4(af[nxt] + 4, aBase + swzA[ks + 1] + 2048);
                        ldsm4(bf[nxt] + 0, wH + swzB[ks + 1]);
                        ldsm4(bf[nxt] + 4, wH + swzB[ks + 1] + 2048);
                    }
                    #pragma unroll
                    for (int nb = 0; nb < 2; nb++) {
                        const uint32_t* a0 = af[cur];
                        const uint32_t* a1 = af[cur] + 4;
                        const uint32_t* bh = bf[cur] + nb * 4;
                        mma16816(acc[0][2 * nb],     a0, bh[0], bh[1]);
                        mma16816(acc[0][2 * nb + 1], a0, bh[2], bh[3]);
                        mma16816(acc[1][2 * nb],     a1, bh[0], bh[1]);
                        mma16816(acc[1][2 * nb + 1], a1, bh[2], bh[3]);
                    }
                }
                BAR_ARRIVE(3 + bsel);                    // buffer free
                c++;
            }

            // ---- epilogue (overlaps with producers running ahead) ----
            const int colq = nh * 32 + (lane & 3) * 2;
            #pragma unroll
            for (int ms = 0; ms < 2; ms++) {
                const int row0 = m0 + mwid * 32 + ms * 16 + (lane >> 2);
                #pragma unroll
                for (int ng = 0; ng < 4; ng++) {
                    const int col = colq + ng * 8;
                    if (row0 < M_) {
                        float* d0 = out + ((size_t)n * M_ + row0) * FOUT_ + col;
                        float2 o0;
                        o0.x = elu1(acc[ms][ng][0] + bb0[ng]);
                        o0.y = elu1(acc[ms][ng][1] + bb1[ng]);
                        *(float2*)d0 = o0;
                    }
                    if (row0 + 8 < M_) {
                        float* d1 = out + ((size_t)n * M_ + row0 + 8) * FOUT_ + col;
                        float2 o1;
                        o1.x = elu1(acc[ms][ng][2] + bb0[ng]);
                        o1.y = elu1(acc[ms][ng][3] + bb1[ng]);
                        *(float2*)d1 = o1;
                    }
                }
            }
        }
    } else {
        // ============== PRODUCERS: gather + fp16 convert + STS ==============
        const int pt = tid - 128;          // 0..127
        const int g8 = pt >> 4;            // row group 0..7
        const int ql = pt & 15;            // 16B gather slice / 8B store slice
        uint32_t soff[8];
        #pragma unroll
        for (int it = 0; it < 8; it++)
            soff[it] = SWZ((uint32_t)((it * 8 + g8) * 128 + ql * 8));
        int c = 0;

        float4 vv[8];
        int tile = blockIdx.x;

        // prologue: prefetch (tile, chunk 0)
        if (tile < NTILES) {
            const int n  = tile / MTILES;
            const int m0 = (tile - n * MTILES) * TM;
            const float* xn = x + (size_t)n * M_ * FIN_;
            #pragma unroll
            for (int it = 0; it < 8; it++) {
                const int m = m0 + it * 8 + g8;
                const int g = (m < M_) ? idx[m * K_ + 0] : 0;
                vv[it] = *(const float4*)(xn + (size_t)g * FIN_ + ql * 4);
            }
        }

        for (; tile < NTILES; tile += gridDim.x) {
            const int n  = tile / MTILES;
            const int m0 = (tile - n * MTILES) * TM;
            const float* xn = x + (size_t)n * M_ * FIN_;

            for (int k = 0; k < K_; k++) {
                const int bsel = c & 1;
                if (c >= 2) BAR_SYNC(3 + bsel);          // wait buffer free

                // convert vv -> fp16 buf bsel
                const uint32_t abase = SA_OFF + bsel * 8192;
                #pragma unroll
                for (int it = 0; it < 8; it++) {
                    float4 a = vv[it];
                    uint32_t h0 = f16p(a.x, a.y), h1 = f16p(a.z, a.w);
                    *(uint2*)(smem + abase + soff[it]) = make_uint2(h0, h1);
                }
                BAR_ARRIVE(1 + bsel);                    // buffer full (release)
                c++;

                // prefetch next chunk (this tile k+1, or next tile chunk 0)
                if (k + 1 < K_) {
                    #pragma unroll
                    for (int it = 0; it < 8; it++) {
                        const int m = m0 + it * 8 + g8;
                        const int g = (m < M_) ? idx[m * K_ + (k + 1)] : 0;
                        vv[it] = *(const float4*)(xn + (size_t)g * FIN_ + ql * 4);
                    }
                } else {
                    const int t2 = tile + gridDim.x;
                    if (t2 < NTILES) {
                        const int n2  = t2 / MTILES;
                        const int m02 = (t2 - n2 * MTILES) * TM;
                        const float* xn2 = x + (size_t)n2 * M_ * FIN_;
                        #pragma unroll
                        for (int it = 0; it < 8; it++) {
                            const int m = m02 + it * 8 + g8;
                            const int g = (m < M_) ? idx[m * K_ + 0] : 0;
                            vv[it] = *(const float4*)(xn2 + (size_t)g * FIN_ + ql * 4);
                        }
                    }
                }
            }
        }
    }
}

extern "C" void kernel_launch(void* const* d_in, const int* in_sizes, int n_in,
                              void* d_out, int out_size)
{
    const float* x    = (const float*)d_in[0];
    const int*   idx  = (const int*)  d_in[1];
    const float* w    = (const float*)d_in[2];
    const float* bias = (const float*)d_in[3];
    float* out = (float*)d_out;

    (void)in_sizes; (void)n_in; (void)out_size;

    cudaFuncSetAttribute(gconv_ws_kernel,
                         cudaFuncAttributeMaxDynamicSharedMemorySize, SMEM_BYTES);

    prep_w_kernel<<<(WELEMS + 255) / 256, 256>>>(w);
    gconv_ws_kernel<<<NBLOCKS, THREADS, SMEM_BYTES>>>(x, idx, bias, out);
}

// round 17
// speedup vs baseline: 4.7031x; 1.0085x over previous
#include <cuda_runtime.h>
#include <cuda_fp16.h>
#include <math.h>
#include <stdint.h>

// ---------------- problem constants ----------------
#define N_    8
#define M_    50000
#define FIN_  64
#define FOUT_ 64
#define K_    9          // real gather fan-in; padded to 10 (chunk 9 = zeros)
#define TM    64         // m rows per tile (2 CTAs/SM)
#define THREADS 256      // warps 0-3 consumers, warps 4-7 producers
#define MTILES  ((M_ + TM - 1) / TM)      // 782
#define NTILES  (N_ * MTILES)             // 6256
#define NBLOCKS 296                       // 2 persistent CTAs per SM
#define ROUNDS  5                         // 10 padded chunks / 2 per round

// ---------------- smem layout (bytes, per CTA) ----------------
// W (fp16) : [9 chunks][64 o x 128B]        = 73728
// A (fp16) : [2 bufs][2 chunks][64 x 128B]  = 32768
#define SB_OFF    0
#define SA_OFF    73728
#define SMEM_BYTES 106496

#define SWZ(b) ((b) ^ (((b) >> 3) & 0x70))

// named barriers: full[s] = 1+s, empty[s] = 3+s; count = all 256 threads
#define BAR_SYNC(id)   asm volatile("bar.sync %0, %1;"   :: "r"(id), "r"(THREADS) : "memory")
#define BAR_ARRIVE(id) asm volatile("bar.arrive %0, %1;" :: "r"(id), "r"(THREADS) : "memory")

// ---------------- ptx helpers ----------------
__device__ __forceinline__ uint32_t smem_u32(const void* p) {
    uint32_t a;
    asm("{ .reg .u64 t; cvta.to.shared.u64 t, %1; cvt.u32.u64 %0, t; }" : "=r"(a) : "l"(p));
    return a;
}
__device__ __forceinline__ void ldsm4(uint32_t* r, uint32_t addr) {
    asm volatile("ldmatrix.sync.aligned.m8n8.x4.shared.b16 {%0,%1,%2,%3}, [%4];"
                 : "=r"(r[0]), "=r"(r[1]), "=r"(r[2]), "=r"(r[3]) : "r"(addr));
}
__device__ __forceinline__ void mma16816(float* c, const uint32_t* a, uint32_t b0, uint32_t b1) {
    asm volatile("mma.sync.aligned.m16n8k16.row.col.f32.f16.f16.f32 "
                 "{%0,%1,%2,%3},{%4,%5,%6,%7},{%8,%9},{%0,%1,%2,%3};"
                 : "+f"(c[0]), "+f"(c[1]), "+f"(c[2]), "+f"(c[3])
                 : "r"(a[0]), "r"(a[1]), "r"(a[2]), "r"(a[3]), "r"(b0), "r"(b1));
}
// fp16x2 pack: low half = a (lower address), high half = b
__device__ __forceinline__ uint32_t f16p(float a, float b) {
    uint32_t r; asm("cvt.rn.f16x2.f32 %0, %1, %2;" : "=r"(r) : "f"(b), "f"(a)); return r;
}
__device__ __forceinline__ float elu1(float v) { return v > 0.0f ? v : expm1f(v); }

// ---------------- weight fp16 scratch: [k][o][i] ----------------
#define WELEMS (K_ * FOUT_ * FIN_)        // 36864
__device__ __half g_Whf[WELEMS];

__global__ void prep_w_kernel(const float* __restrict__ w) {
    int t = blockIdx.x * blockDim.x + threadIdx.x;
    if (t < WELEMS) {
        int k = t >> 12;
        int rr = t & 4095;
        int o = rr >> 6, i = rr & 63;
        g_Whf[t] = __float2half_rn(w[o * (K_ * FIN_) + k * FIN_ + i]);
    }
}

// ---------------- main kernel ----------------
__global__ __launch_bounds__(THREADS, 2)
void gconv_ws_kernel(const float* __restrict__ x,
                     const int*   __restrict__ idx,
                     const float* __restrict__ bias,
                     float*       __restrict__ out)
{
    extern __shared__ char smem[];
    const uint32_t sb = smem_u32(smem);
    const int tid  = threadIdx.x;
    const int wid  = tid >> 5;
    const int lane = tid & 31;

    // ---- stage fp16 weights into smem with swizzle (once per persistent CTA) ----
    for (int j = tid; j < K_ * 512; j += THREADS) {          // 16B units
        uint4 v = ((const uint4*)g_Whf)[j];
        int t8k = j >> 9, u = j & 511;
        *(uint4*)(smem + SB_OFF + t8k * 8192 + SWZ(u * 16)) = v;
    }
    __syncthreads();

    if (wid < 4) {
        // ======== CONSUMERS: 32m x 32n warp tiles, 2 chunks per sync ========
        const int mwid = wid & 1;          // m-group: rows mwid*32..+32
        const int nh   = wid >> 1;         // n-half: cols nh*32..+32

        float bb0[4], bb1[4];
        #pragma unroll
        for (int ng = 0; ng < 4; ng++) {
            int col = nh * 32 + ng * 8 + (lane & 3) * 2;
            bb0[ng] = bias[col];
            bb1[ng] = bias[col + 1];
        }

        const uint32_t aoff0 = (uint32_t)((mwid * 32 + (lane & 15)) * 128 + (lane >> 4) * 16);
        const uint32_t boff0 = (uint32_t)((((lane >> 4) & 1) * 8 + (lane & 7)) * 128
                                          + ((lane >> 3) & 1) * 16);
        uint32_t swzA[4], swzB[4];
        #pragma unroll
        for (int ks = 0; ks < 4; ks++) {
            swzA[ks] = SWZ(aoff0 + ks * 32);
            swzB[ks] = SWZ(boff0 + ks * 32);
        }
        int c = 0;   // global round counter (matches producer's)

        for (int tile = blockIdx.x; tile < NTILES; tile += gridDim.x) {
            const int n  = tile / MTILES;
            const int mt = tile - n * MTILES;
            const int m0 = mt * TM;

            float acc[2][4][4];
            #pragma unroll
            for (int ms = 0; ms < 2; ms++)
                #pragma unroll
                for (int a = 0; a < 4; a++)
                    #pragma unroll
                    for (int cc = 0; cc < 4; cc++) acc[ms][a][cc] = 0.0f;

            for (int r = 0; r < ROUNDS; r++) {
                const int s = c & 1;
                BAR_SYNC(1 + s);                         // wait buffer full

                const uint32_t bufB = sb + SA_OFF + s * 16384;

                #pragma unroll
                for (int ch = 0; ch < 2; ch++) {
                    const int k  = 2 * r + ch;
                    const int wk = (k < K_) ? k : 0;     // chunk 9: A is zeros, 0*W0 = 0
                    const uint32_t aBase = bufB + ch * 8192;
                    const uint32_t wH = sb + SB_OFF + wk * 8192 + nh * 4096;

                    uint32_t af[2][8], bf[2][8];
                    ldsm4(af[0] + 0, aBase + swzA[0]);
                    ldsm4(af[0] + 4, aBase + swzA[0] + 2048);
                    ldsm4(bf[0] + 0, wH + swzB[0]);
                    ldsm4(bf[0] + 4, wH + swzB[0] + 2048);

                    #pragma unroll
                    for (int ks = 0; ks < 4; ks++) {
                        const int cur = ks & 1, nxt = cur ^ 1;
                        if (ks < 3) {                    // prefetch ks+1 under mma
                            ldsm4(af[nxt] + 0, aBase + swzA[ks + 1]);
                            ldsm4(af[nxt] + 4, aBase + swzA[ks + 1] + 2048);
                            ldsm4(bf[nxt] + 0, wH + swzB[ks + 1]);
                            ldsm4(bf[nxt] + 4, wH + swzB[ks + 1] + 2048);
                        }
                        #pragma unroll
                        for (int nb = 0; nb < 2; nb++) {
                            const uint32_t* a0 = af[cur];
                            const uint32_t* a1 = af[cur] + 4;
                            const uint32_t* bh = bf[cur] + nb * 4;
                            mma16816(acc[0][2 * nb],     a0, bh[0], bh[1]);
                            mma16816(acc[0][2 * nb + 1], a0, bh[2], bh[3]);
                            mma16816(acc[1][2 * nb],     a1, bh[0], bh[1]);
                            mma16816(acc[1][2 * nb + 1], a1, bh[2], bh[3]);
                        }
                    }
                }
                BAR_ARRIVE(3 + s);                       // buffer free
                c++;
            }

            // ---- epilogue (overlaps with producers running ahead) ----
            const int colq = nh * 32 + (lane & 3) * 2;
            #pragma unroll
            for (int ms = 0; ms < 2; ms++) {
                const int row0 = m0 + mwid * 32 + ms * 16 + (lane >> 2);
                #pragma unroll
                for (int ng = 0; ng < 4; ng++) {
                    const int col = colq + ng * 8;
                    if (row0 < M_) {
                        float* d0 = out + ((size_t)n * M_ + row0) * FOUT_ + col;
                        float2 o0;
                        o0.x = elu1(acc[ms][ng][0] + bb0[ng]);
                        o0.y = elu1(acc[ms][ng][1] + bb1[ng]);
                        *(float2*)d0 = o0;
                    }
                    if (row0 + 8 < M_) {
                        float* d1 = out + ((size_t)n * M_ + row0 + 8) * FOUT_ + col;
                        float2 o1;
                        o1.x = elu1(acc[ms][ng][2] + bb0[ng]);
                        o1.y = elu1(acc[ms][ng][3] + bb1[ng]);
                        *(float2*)d1 = o1;
                    }
                }
            }
        }
    } else {
        // ====== PRODUCERS: gather + fp16 convert + STS, 2 chunks per sync ======
        const int pt = tid - 128;          // 0..127
        const int g8 = pt >> 4;            // row group 0..7
        const int ql = pt & 15;            // 16B gather slice / 8B store slice
        uint32_t soff[8];
        #pragma unroll
        for (int it = 0; it < 8; it++)
            soff[it] = SWZ((uint32_t)((it * 8 + g8) * 128 + ql * 8));
        int c = 0;

        const float4 zero4 = make_float4(0.f, 0.f, 0.f, 0.f);
        float4 vv[8], ww[8];               // chunk 2r, chunk 2r+1 staging

        // prologue: prefetch round 0 of first tile (k0=0, k1=1 both real)
        {
            const int tile0 = blockIdx.x;
            if (tile0 < NTILES) {
                const int n  = tile0 / MTILES;
                const int m0 = (tile0 - n * MTILES) * TM;
                const float* xn = x + (size_t)n * M_ * FIN_;
                #pragma unroll
                for (int it = 0; it < 8; it++) {
                    const int m = m0 + it * 8 + g8;
                    const int g0 = (m < M_) ? idx[m * K_ + 0] : 0;
                    const int g1 = (m < M_) ? idx[m * K_ + 1] : 0;
                    vv[it] = *(const float4*)(xn + (size_t)g0 * FIN_ + ql * 4);
                    ww[it] = *(const float4*)(xn + (size_t)g1 * FIN_ + ql * 4);
                }
            }
        }

        for (int tile = blockIdx.x; tile < NTILES; tile += gridDim.x) {
            const int n  = tile / MTILES;
            const int m0 = (tile - n * MTILES) * TM;
            const float* xn = x + (size_t)n * M_ * FIN_;

            for (int r = 0; r < ROUNDS; r++) {
                const int s = c & 1;
                if (c >= 2) BAR_SYNC(3 + s);             // wait buffer free

                // convert staged chunks -> buf s (both slots, unconditionally)
                const uint32_t abase = SA_OFF + s * 16384;
                #pragma unroll
                for (int it = 0; it < 8; it++) {
                    float4 a = vv[it];
                    *(uint2*)(smem + abase + soff[it]) =
                        make_uint2(f16p(a.x, a.y), f16p(a.z, a.w));
                }
                #pragma unroll
                for (int it = 0; it < 8; it++) {
                    float4 a = ww[it];
                    *(uint2*)(smem + abase + 8192 + soff[it]) =
                        make_uint2(f16p(a.x, a.y), f16p(a.z, a.w));
                }
                BAR_ARRIVE(1 + s);                       // buffer full (release)
                c++;

                // prefetch next round's chunks (uniform; k1==9 -> zeros)
                if (r + 1 < ROUNDS) {
                    const int k0 = 2 * r + 2;            // 2,4,6,8 (all real)
                    const int k1 = k0 + 1;               // 3,5,7,9
                    #pragma unroll
                    for (int it = 0; it < 8; it++) {
                        const int m = m0 + it * 8 + g8;
                        const int g0 = (m < M_) ? idx[m * K_ + k0] : 0;
                        vv[it] = *(const float4*)(xn + (size_t)g0 * FIN_ + ql * 4);
                    }
                    if (k1 < K_) {
                        #pragma unroll
                        for (int it = 0; it < 8; it++) {
                            const int m = m0 + it * 8 + g8;
                            const int g1 = (m < M_) ? idx[m * K_ + k1] : 0;
                            ww[it] = *(const float4*)(xn + (size_t)g1 * FIN_ + ql * 4);
                        }
                    } else {
                        #pragma unroll
                        for (int it = 0; it < 8; it++) ww[it] = zero4;
                    }
                } else {
                    const int t2 = tile + gridDim.x;
                    if (t2 < NTILES) {
                        const int n2  = t2 / MTILES;
                        const int m02 = (t2 - n2 * MTILES) * TM;
                        const float* xn2 = x + (size_t)n2 * M_ * FIN_;
                        #pragma unroll
                        for (int it = 0; it < 8; it++) {
                            const int m = m02 + it * 8 + g8;
                            const int g0 = (m < M_) ? idx[m * K_ + 0] : 0;
                            const int g1 = (m < M_) ? idx[m * K_ + 1] : 0;
                            vv[it] = *(const float4*)(xn2 + (size_t)g0 * FIN_ + ql * 4);
                            ww[it] = *(const float4*)(xn2 + (size_t)g1 * FIN_ + ql * 4);
                        }
                    }
                }
            }
        }
    }
}

extern "C" void kernel_launch(void* const* d_in, const int* in_sizes, int n_in,
                              void* d_out, int out_size)
{
    const float* x    = (const float*)d_in[0];
    const int*   idx  = (const int*)  d_in[1];
    const float* w    = (const float*)d_in[2];
    const float* bias = (const float*)d_in[3];
    float* out = (float*)d_out;

    (void)in_sizes; (void)n_in; (void)out_size;

    cudaFuncSetAttribute(gconv_ws_kernel,
                         cudaFuncAttributeMaxDynamicSharedMemorySize, SMEM_BYTES);

    prep_w_kernel<<<(WELEMS + 255) / 256, 256>>>(w);
    gconv_ws_kernel<<<NBLOCKS, THREADS, SMEM_BYTES>>>(x, idx, bias, out);
}